// round 8
// baseline (speedup 1.0000x reference)
#include <cuda_runtime.h>
#include <math.h>
#include <stdint.h>

#define E_    1024
#define H_    16
#define DH    64
#define B_    4
#define N_    1024
#define ROWS  (B_ * N_)      // 4096
#define FF    (4 * E_)       // 4096
#define MAXLEN 512

// ---------------- scratch (no allocs allowed) ----------------
__device__ float g_xn[ROWS * E_];
__device__ float g_qkv[ROWS * 3 * E_];
__device__ float g_o[ROWS * E_];
__device__ float g_xm[ROWS * E_];
__device__ float g_hbuf[ROWS * FF];
__device__ float g_wqkv[3 * E_ * E_];
__device__ float g_wout[E_ * E_];
__device__ float g_w1[FF * E_];
__device__ float g_w2[E_ * FF];

__device__ __forceinline__ uint32_t cvt_tf32(float f) {
    uint32_t r;
    asm("cvt.rna.tf32.f32 %0, %1;" : "=r"(r) : "f"(f));
    return r;
}

__device__ __forceinline__ void mma_tf32(float* c, const uint32_t* a, const uint32_t* b) {
    asm volatile(
        "mma.sync.aligned.m16n8k8.row.col.f32.tf32.tf32.f32 "
        "{%0,%1,%2,%3}, {%4,%5,%6,%7}, {%8,%9}, {%0,%1,%2,%3};"
        : "+f"(c[0]), "+f"(c[1]), "+f"(c[2]), "+f"(c[3])
        : "r"(a[0]), "r"(a[1]), "r"(a[2]), "r"(a[3]), "r"(b[0]), "r"(b[1]));
}

__device__ __forceinline__ void cp16(uint32_t smem_addr, const void* gptr) {
    asm volatile("cp.async.cg.shared.global [%0], [%1], 16;"
                 :: "r"(smem_addr), "l"(gptr) : "memory");
}
#define CP_COMMIT() asm volatile("cp.async.commit_group;" ::: "memory")
#define CP_WAIT2()  asm volatile("cp.async.wait_group 2;" ::: "memory")
#define CP_WAIT1()  asm volatile("cp.async.wait_group 1;" ::: "memory")

// ---------------- weight rounding ----------------
__global__ void round_kernel(const float* __restrict__ in, float* __restrict__ out) {
    int i = (blockIdx.x * blockDim.x + threadIdx.x) * 4;
    float4 v = *(const float4*)(in + i);
    uint4 o;
    o.x = cvt_tf32(v.x); o.y = cvt_tf32(v.y);
    o.z = cvt_tf32(v.z); o.w = cvt_tf32(v.w);
    *(uint4*)(out + i) = o;
}

// ---------------- LayerNorm (emits tf32-rounded output) ----------------
__global__ void ln_kernel(const float* __restrict__ x, const float* __restrict__ g,
                          const float* __restrict__ bt, float* __restrict__ out) {
    int row = blockIdx.x;
    int tid = threadIdx.x;
    const float4* xr = (const float4*)(x + (size_t)row * E_);
    float4 v = xr[tid];
    float s  = v.x + v.y + v.z + v.w;
    float s2 = v.x*v.x + v.y*v.y + v.z*v.z + v.w*v.w;
    #pragma unroll
    for (int o = 16; o; o >>= 1) {
        s  += __shfl_xor_sync(0xffffffffu, s,  o);
        s2 += __shfl_xor_sync(0xffffffffu, s2, o);
    }
    __shared__ float ws[8], ws2[8];
    int w = tid >> 5;
    if ((tid & 31) == 0) { ws[w] = s; ws2[w] = s2; }
    __syncthreads();
    if (tid < 32) {
        float a  = (tid < 8) ? ws[tid]  : 0.f;
        float a2 = (tid < 8) ? ws2[tid] : 0.f;
        #pragma unroll
        for (int o = 4; o; o >>= 1) {
            a  += __shfl_xor_sync(0xffffffffu, a,  o);
            a2 += __shfl_xor_sync(0xffffffffu, a2, o);
        }
        if (tid == 0) {
            float mu  = a / (float)E_;
            float var = a2 / (float)E_ - mu * mu;
            ws[0]  = mu;
            ws2[0] = rsqrtf(var + 1e-5f);
        }
    }
    __syncthreads();
    float mu = ws[0], rstd = ws2[0];
    float4 gv = ((const float4*)g)[tid];
    float4 bv = ((const float4*)bt)[tid];
    uint4 ov;
    ov.x = cvt_tf32((v.x - mu) * rstd * gv.x + bv.x);
    ov.y = cvt_tf32((v.y - mu) * rstd * gv.y + bv.y);
    ov.z = cvt_tf32((v.z - mu) * rstd * gv.z + bv.z);
    ov.w = cvt_tf32((v.w - mu) * rstd * gv.w + bv.w);
    ((uint4*)(out + (size_t)row * E_))[tid] = ov;
}

// ---------------- tf32 GEMM (round-5 proven version) ----------------
#define BK      16
#define SST     20
#define STAGES  4
#define STAGE_ELTS (128 * SST)
#define GSMEM_BYTES (STAGES * STAGE_ELTS * 2 * 4)

__global__ void __launch_bounds__(128, 2)
gemm_tc(const float* __restrict__ A, const float* __restrict__ W,
        const float* __restrict__ bias, const float* __restrict__ res,
        float* __restrict__ C, int M, int Nn, int K, int relu, int round_out) {
    extern __shared__ float smem[];
    float* SA = smem;
    float* SB = smem + STAGES * STAGE_ELTS;
    uint32_t sa_u = (uint32_t)__cvta_generic_to_shared(SA);
    uint32_t sb_u = (uint32_t)__cvta_generic_to_shared(SB);

    int tid = threadIdx.x;
    int wid = tid >> 5, lane = tid & 31;
    int g = lane >> 2, t = lane & 3;
    int wm = wid >> 1, wn = wid & 1;
    int bm = blockIdx.y * 128, bn = blockIdx.x * 128;

    int lrow = tid >> 2, lc4 = tid & 3;
    const float* Ag = A + (size_t)(bm + lrow) * K + lc4 * 4;
    const float* Wg = W + (size_t)(bn + lrow) * K + lc4 * 4;
    uint32_t soff = (uint32_t)((lrow * SST + lc4 * 4) * 4);

    float acc[4][8][4];
    #pragma unroll
    for (int i = 0; i < 4; i++)
        #pragma unroll
        for (int j = 0; j < 8; j++)
            #pragma unroll
            for (int v = 0; v < 4; v++) acc[i][j][v] = 0.f;

    int S = K / BK;

    auto issue = [&](int s) {
        int st = s & (STAGES - 1);
        int koff = s * BK;
        uint32_t sbase = (uint32_t)(st * STAGE_ELTS * 4) + soff;
        #pragma unroll
        for (int i = 0; i < 4; i++) {
            cp16(sa_u + sbase + i * 32 * SST * 4, Ag + (size_t)i * 32 * K + koff);
            cp16(sb_u + sbase + i * 32 * SST * 4, Wg + (size_t)i * 32 * K + koff);
        }
        CP_COMMIT();
    };

    issue(0); issue(1); issue(2);

    for (int s = 0; s < S; s++) {
        CP_WAIT2();
        __syncthreads();
        if (s + 3 < S) issue(s + 3);
        else CP_COMMIT();

        int st = s & (STAGES - 1);
        const uint32_t* sa = (const uint32_t*)(SA + st * STAGE_ELTS);
        const uint32_t* sb = (const uint32_t*)(SB + st * STAGE_ELTS);
        #pragma unroll
        for (int ks = 0; ks < 2; ks++) {
            int ko = ks * 8 + t;
            uint32_t af[4][4];
            #pragma unroll
            for (int mi = 0; mi < 4; mi++) {
                int r0 = wm * 64 + mi * 16 + g;
                af[mi][0] = sa[r0 * SST + ko];
                af[mi][1] = sa[(r0 + 8) * SST + ko];
                af[mi][2] = sa[r0 * SST + ko + 4];
                af[mi][3] = sa[(r0 + 8) * SST + ko + 4];
            }
            uint32_t bf[8][2];
            #pragma unroll
            for (int ni = 0; ni < 8; ni++) {
                int rn = wn * 64 + ni * 8 + g;
                bf[ni][0] = sb[rn * SST + ko];
                bf[ni][1] = sb[rn * SST + ko + 4];
            }
            #pragma unroll
            for (int mi = 0; mi < 4; mi++)
                #pragma unroll
                for (int ni = 0; ni < 8; ni++)
                    mma_tf32(acc[mi][ni], af[mi], bf[ni]);
        }
    }

    #pragma unroll
    for (int mi = 0; mi < 4; mi++) {
        int r0 = bm + wm * 64 + mi * 16 + g;
        #pragma unroll
        for (int half = 0; half < 2; half++) {
            int row = r0 + half * 8;
            float* crow = C + (size_t)row * Nn + bn + wn * 64;
            const float* rrow = res ? res + (size_t)row * Nn + bn + wn * 64 : nullptr;
            const float* brow = bias + bn + wn * 64;
            #pragma unroll
            for (int ni = 0; ni < 8; ni++) {
                int col = ni * 8 + 2 * t;
                float v0 = acc[mi][ni][half * 2 + 0] + brow[col];
                float v1 = acc[mi][ni][half * 2 + 1] + brow[col + 1];
                if (relu) { v0 = fmaxf(v0, 0.f); v1 = fmaxf(v1, 0.f); }
                if (rrow) { v0 += rrow[col]; v1 += rrow[col + 1]; }
                if (round_out) {
                    uint2 u = make_uint2(cvt_tf32(v0), cvt_tf32(v1));
                    *(uint2*)(crow + col) = u;
                } else {
                    *(float2*)(crow + col) = make_float2(v0, v1);
                }
            }
        }
    }
}

// ---------------- Tensor-core windowed attention, cp.async double buffer -----
#define KST 68
#define VST 72
#define KR_ELTS (32 * KST)
#define VR_ELTS (32 * VST)
#define ASMEM_BYTES ((2 * KR_ELTS + 2 * VR_ELTS + 128 * 36) * 4)

__global__ void __launch_bounds__(256)
attn_kernel(const float* __restrict__ qkv, const float* __restrict__ rel_pos,
            float* __restrict__ o) {
    extern __shared__ float asmem[];
    float* Kr = asmem;                       // 2 bufs
    float* Vr = asmem + 2 * KR_ELTS;
    uint32_t* Ps = (uint32_t*)(asmem + 2 * KR_ELTS + 2 * VR_ELTS);
    uint32_t kr_u = (uint32_t)__cvta_generic_to_shared(Kr);
    uint32_t vr_u = (uint32_t)__cvta_generic_to_shared(Vr);

    int tid = threadIdx.x;
    int wid = tid >> 5, lane = tid & 31;
    int g = lane >> 2, t = lane & 3;
    int b = blockIdx.z, h = blockIdx.y;
    int qs = blockIdx.x * 128;
    const float* base = qkv + (size_t)b * N_ * 3 * E_;
    const float* rp = rel_pos + h * MAXLEN;

    int row0 = qs + wid * 16 + g;
    uint32_t qf[8][4];
    {
        const float* q0 = base + (size_t)row0 * 3 * E_ + h * DH;
        const float* q1 = q0 + (size_t)8 * 3 * E_;
        #pragma unroll
        for (int kk = 0; kk < 8; kk++) {
            qf[kk][0] = cvt_tf32(0.125f * q0[kk * 8 + t]);
            qf[kk][1] = cvt_tf32(0.125f * q1[kk * 8 + t]);
            qf[kk][2] = cvt_tf32(0.125f * q0[kk * 8 + t + 4]);
            qf[kk][3] = cvt_tf32(0.125f * q1[kk * 8 + t + 4]);
        }
    }

    float oacc[8][4];
    #pragma unroll
    for (int i = 0; i < 8; i++)
        #pragma unroll
        for (int v = 0; v < 4; v++) oacc[i][v] = 0.f;
    float m_o[2] = {-INFINITY, -INFINITY};
    float lac[2] = {0.f, 0.f};

    int kt_lo = max(0, qs - (MAXLEN - 1)) >> 5;
    int kt_hi = (qs + 127) >> 5;

    int jrow = tid >> 3;
    int d0 = (tid & 7) * 8;
    const float* kgbase = base + E_ + h * DH + d0;
    const float* vgbase = base + 2 * E_ + h * DH + d0;

    auto issueKV = [&](int kt, int buf) {
        int ks0 = kt * 32;
        const float* kp = kgbase + (size_t)(ks0 + jrow) * 3 * E_;
        const float* vp = vgbase + (size_t)(ks0 + jrow) * 3 * E_;
        uint32_t kd = kr_u + (uint32_t)((buf * KR_ELTS + jrow * KST + d0) * 4);
        uint32_t vd = vr_u + (uint32_t)((buf * VR_ELTS + jrow * VST + d0) * 4);
        cp16(kd, kp); cp16(kd + 16, kp + 4);
        cp16(vd, vp); cp16(vd + 16, vp + 4);
        CP_COMMIT();
    };

    issueKV(kt_lo, 0);

    for (int kt = kt_lo; kt <= kt_hi; kt++) {
        int buf = (kt - kt_lo) & 1;
        __syncthreads();            // everyone done with buf^1's previous tile
        if (kt + 1 <= kt_hi) issueKV(kt + 1, buf ^ 1);
        else CP_COMMIT();
        CP_WAIT1();                 // current tile's group complete
        __syncthreads();

        const float* Kb = Kr + buf * KR_ELTS;
        const float* Vb = Vr + buf * VR_ELTS;
        int ks0 = kt * 32;

        // ---- S = (Q/8) K^T ----
        float sacc[4][4];
        #pragma unroll
        for (int ni = 0; ni < 4; ni++)
            #pragma unroll
            for (int v = 0; v < 4; v++) sacc[ni][v] = 0.f;
        #pragma unroll
        for (int kk = 0; kk < 8; kk++) {
            uint32_t bf[4][2];
            #pragma unroll
            for (int ni = 0; ni < 4; ni++) {
                int rn = ni * 8 + g;
                bf[ni][0] = cvt_tf32(Kb[rn * KST + kk * 8 + t]);
                bf[ni][1] = cvt_tf32(Kb[rn * KST + kk * 8 + t + 4]);
            }
            #pragma unroll
            for (int ni = 0; ni < 4; ni++)
                mma_tf32(sacc[ni], qf[kk], bf[ni]);
        }

        // ---- bias + mask + online softmax ----
        float m_t[2] = {-INFINITY, -INFINITY};
        #pragma unroll
        for (int ni = 0; ni < 4; ni++) {
            #pragma unroll
            for (int v = 0; v < 4; v++) {
                int r = v >> 1;
                int i_glob = row0 + r * 8;
                int j = ks0 + ni * 8 + 2 * t + (v & 1);
                int rel = i_glob - j;
                float val;
                if (rel >= 0 && rel < MAXLEN) val = sacc[ni][v] + __ldg(rp + rel);
                else                          val = -INFINITY;
                sacc[ni][v] = val;
                m_t[r] = fmaxf(m_t[r], val);
            }
        }
        #pragma unroll
        for (int r = 0; r < 2; r++) {
            m_t[r] = fmaxf(m_t[r], __shfl_xor_sync(0xffffffffu, m_t[r], 1));
            m_t[r] = fmaxf(m_t[r], __shfl_xor_sync(0xffffffffu, m_t[r], 2));
        }
        float fac[2], m_n[2];
        #pragma unroll
        for (int r = 0; r < 2; r++) {
            m_n[r] = fmaxf(m_o[r], m_t[r]);
            fac[r] = (m_n[r] == -INFINITY) ? 1.f : __expf(m_o[r] - m_n[r]);
            if (m_o[r] == -INFINITY) fac[r] = 0.f;
            if (m_n[r] == -INFINITY) fac[r] = 1.f;
        }
        float psum[2] = {0.f, 0.f};
        int lrow0 = wid * 16 + g;
        #pragma unroll
        for (int ni = 0; ni < 4; ni++) {
            #pragma unroll
            for (int v = 0; v < 4; v++) {
                int r = v >> 1;
                float p = (m_n[r] == -INFINITY) ? 0.f : __expf(sacc[ni][v] - m_n[r]);
                psum[r] += p;
                Ps[(lrow0 + r * 8) * 36 + ni * 8 + 2 * t + (v & 1)] = cvt_tf32(p);
            }
        }
        #pragma unroll
        for (int r = 0; r < 2; r++) {
            psum[r] += __shfl_xor_sync(0xffffffffu, psum[r], 1);
            psum[r] += __shfl_xor_sync(0xffffffffu, psum[r], 2);
            lac[r] = lac[r] * fac[r] + psum[r];
            m_o[r] = m_n[r];
        }
        #pragma unroll
        for (int i = 0; i < 8; i++) {
            oacc[i][0] *= fac[0]; oacc[i][1] *= fac[0];
            oacc[i][2] *= fac[1]; oacc[i][3] *= fac[1];
        }
        __syncwarp();

        // ---- O += P V ----
        #pragma unroll
        for (int kk = 0; kk < 4; kk++) {
            uint32_t af[4];
            af[0] = Ps[lrow0 * 36 + kk * 8 + t];
            af[1] = Ps[(lrow0 + 8) * 36 + kk * 8 + t];
            af[2] = Ps[lrow0 * 36 + kk * 8 + t + 4];
            af[3] = Ps[(lrow0 + 8) * 36 + kk * 8 + t + 4];
            #pragma unroll
            for (int ni = 0; ni < 8; ni++) {
                uint32_t bf[2];
                bf[0] = cvt_tf32(Vb[(kk * 8 + t) * VST + ni * 8 + g]);
                bf[1] = cvt_tf32(Vb[(kk * 8 + t + 4) * VST + ni * 8 + g]);
                mma_tf32(oacc[ni], af, bf);
            }
        }
        __syncwarp();
    }

    float inv0 = 1.f / lac[0];
    float inv1 = 1.f / lac[1];
    float* op0 = o + ((size_t)(b * N_) + row0) * E_ + h * DH;
    float* op1 = op0 + (size_t)8 * E_;
    #pragma unroll
    for (int ni = 0; ni < 8; ni++) {
        int col = ni * 8 + 2 * t;
        uint2 u0 = make_uint2(cvt_tf32(oacc[ni][0] * inv0), cvt_tf32(oacc[ni][1] * inv0));
        uint2 u1 = make_uint2(cvt_tf32(oacc[ni][2] * inv1), cvt_tf32(oacc[ni][3] * inv1));
        *(uint2*)(op0 + col) = u0;
        *(uint2*)(op1 + col) = u1;
    }
}

// ---------------- driver (single stream, no static state) ----------------
extern "C" void kernel_launch(void* const* d_in, const int* in_sizes, int n_in,
                              void* d_out, int out_size) {
    const float* x         = (const float*)d_in[0];
    const float* rel_pos   = (const float*)d_in[1];
    const float* in_proj_w = (const float*)d_in[2];
    const float* in_proj_b = (const float*)d_in[3];
    const float* out_w     = (const float*)d_in[4];
    const float* out_b     = (const float*)d_in[5];
    const float* w1        = (const float*)d_in[6];
    const float* b1        = (const float*)d_in[7];
    const float* w2        = (const float*)d_in[8];
    const float* b2        = (const float*)d_in[9];
    const float* ln1_g     = (const float*)d_in[10];
    const float* ln1_b     = (const float*)d_in[11];
    const float* ln2_g     = (const float*)d_in[12];
    const float* ln2_b     = (const float*)d_in[13];
    float* out = (float*)d_out;

    float *xn, *qkv, *o, *xm, *hbuf, *wqkv, *wout, *w1r, *w2r;
    cudaGetSymbolAddress((void**)&xn,   g_xn);
    cudaGetSymbolAddress((void**)&qkv,  g_qkv);
    cudaGetSymbolAddress((void**)&o,    g_o);
    cudaGetSymbolAddress((void**)&xm,   g_xm);
    cudaGetSymbolAddress((void**)&hbuf, g_hbuf);
    cudaGetSymbolAddress((void**)&wqkv, g_wqkv);
    cudaGetSymbolAddress((void**)&wout, g_wout);
    cudaGetSymbolAddress((void**)&w1r,  g_w1);
    cudaGetSymbolAddress((void**)&w2r,  g_w2);

    cudaFuncSetAttribute(gemm_tc, cudaFuncAttributeMaxDynamicSharedMemorySize,
                         GSMEM_BYTES);
    cudaFuncSetAttribute(attn_kernel, cudaFuncAttributeMaxDynamicSharedMemorySize,
                         ASMEM_BYTES);

    // weight pre-rounding (tf32 rna)
    round_kernel<<<3 * E_ * E_ / 1024, 256>>>(in_proj_w, wqkv);
    round_kernel<<<E_ * E_ / 1024, 256>>>(out_w, wout);
    round_kernel<<<FF * E_ / 1024, 256>>>(w1, w1r);
    round_kernel<<<E_ * FF / 1024, 256>>>(w2, w2r);

    ln_kernel<<<ROWS, 256>>>(x, ln1_g, ln1_b, xn);
    gemm_tc<<<dim3(3 * E_ / 128, ROWS / 128), 128, GSMEM_BYTES>>>(
        xn, wqkv, in_proj_b, nullptr, qkv, ROWS, 3 * E_, E_, 0, 0);
    attn_kernel<<<dim3(N_ / 128, H_, B_), 256, ASMEM_BYTES>>>(qkv, rel_pos, o);
    gemm_tc<<<dim3(E_ / 128, ROWS / 128), 128, GSMEM_BYTES>>>(
        o, wout, out_b, x, out, ROWS, E_, E_, 0, 0);
    ln_kernel<<<ROWS, 256>>>(out, ln2_g, ln2_b, xm);
    gemm_tc<<<dim3(FF / 128, ROWS / 128), 128, GSMEM_BYTES>>>(
        xm, w1r, b1, nullptr, hbuf, ROWS, FF, E_, 1, 1);
    gemm_tc<<<dim3(E_ / 128, ROWS / 128), 128, GSMEM_BYTES>>>(
        hbuf, w2r, b2, out, out, ROWS, E_, FF, 0, 0);
}

// round 9
// speedup vs baseline: 1.6125x; 1.6125x over previous
#include <cuda_runtime.h>
#include <cuda_fp16.h>
#include <math.h>
#include <stdint.h>

#define E_    1024
#define H_    16
#define DH    64
#define B_    4
#define N_    1024
#define ROWS  (B_ * N_)      // 4096
#define FF    (4 * E_)       // 4096
#define MAXLEN 512

// ---------------- scratch (no allocs allowed) ----------------
__device__ __half g_xn[ROWS * E_];         // LN1 out (fp16)
__device__ float  g_qkv[ROWS * 3 * E_];    // QKV (fp32, attention input)
__device__ __half g_o[ROWS * E_];          // attention out (fp16)
__device__ __half g_xm[ROWS * E_];         // LN2 out (fp16)
__device__ __half g_hbuf[ROWS * FF];       // FFN hidden (fp16)
__device__ __half g_wqkv[3 * E_ * E_];
__device__ __half g_wout[E_ * E_];
__device__ __half g_w1[FF * E_];
__device__ __half g_w2[E_ * FF];

__device__ __forceinline__ uint32_t cvt_tf32(float f) {
    uint32_t r;
    asm("cvt.rna.tf32.f32 %0, %1;" : "=r"(r) : "f"(f));
    return r;
}

__device__ __forceinline__ void mma_tf32(float* c, const uint32_t* a, const uint32_t* b) {
    asm volatile(
        "mma.sync.aligned.m16n8k8.row.col.f32.tf32.tf32.f32 "
        "{%0,%1,%2,%3}, {%4,%5,%6,%7}, {%8,%9}, {%0,%1,%2,%3};"
        : "+f"(c[0]), "+f"(c[1]), "+f"(c[2]), "+f"(c[3])
        : "r"(a[0]), "r"(a[1]), "r"(a[2]), "r"(a[3]), "r"(b[0]), "r"(b[1]));
}

__device__ __forceinline__ void mma_f16(float* c, const uint32_t* a, const uint32_t* b) {
    asm volatile(
        "mma.sync.aligned.m16n8k16.row.col.f32.f16.f16.f32 "
        "{%0,%1,%2,%3}, {%4,%5,%6,%7}, {%8,%9}, {%0,%1,%2,%3};"
        : "+f"(c[0]), "+f"(c[1]), "+f"(c[2]), "+f"(c[3])
        : "r"(a[0]), "r"(a[1]), "r"(a[2]), "r"(a[3]), "r"(b[0]), "r"(b[1]));
}

__device__ __forceinline__ void cp16(uint32_t smem_addr, const void* gptr) {
    asm volatile("cp.async.cg.shared.global [%0], [%1], 16;"
                 :: "r"(smem_addr), "l"(gptr) : "memory");
}
#define CP_COMMIT() asm volatile("cp.async.commit_group;" ::: "memory")
#define CP_WAIT2()  asm volatile("cp.async.wait_group 2;" ::: "memory")
#define CP_WAIT1()  asm volatile("cp.async.wait_group 1;" ::: "memory")

// ---------------- weight conversion fp32 -> fp16 ----------------
__global__ void cvt_half_kernel(const float* __restrict__ in, __half* __restrict__ out) {
    int i = (blockIdx.x * blockDim.x + threadIdx.x) * 4;
    float4 v = *(const float4*)(in + i);
    __half2 h0 = __floats2half2_rn(v.x, v.y);
    __half2 h1 = __floats2half2_rn(v.z, v.w);
    uint2 u = make_uint2(*(uint32_t*)&h0, *(uint32_t*)&h1);
    *(uint2*)(out + i) = u;
}

// ---------------- LayerNorm (emits fp16) ----------------
__global__ void ln_kernel(const float* __restrict__ x, const float* __restrict__ g,
                          const float* __restrict__ bt, __half* __restrict__ out) {
    int row = blockIdx.x;
    int tid = threadIdx.x;
    const float4* xr = (const float4*)(x + (size_t)row * E_);
    float4 v = xr[tid];
    float s  = v.x + v.y + v.z + v.w;
    float s2 = v.x*v.x + v.y*v.y + v.z*v.z + v.w*v.w;
    #pragma unroll
    for (int o = 16; o; o >>= 1) {
        s  += __shfl_xor_sync(0xffffffffu, s,  o);
        s2 += __shfl_xor_sync(0xffffffffu, s2, o);
    }
    __shared__ float ws[8], ws2[8];
    int w = tid >> 5;
    if ((tid & 31) == 0) { ws[w] = s; ws2[w] = s2; }
    __syncthreads();
    if (tid < 32) {
        float a  = (tid < 8) ? ws[tid]  : 0.f;
        float a2 = (tid < 8) ? ws2[tid] : 0.f;
        #pragma unroll
        for (int o = 4; o; o >>= 1) {
            a  += __shfl_xor_sync(0xffffffffu, a,  o);
            a2 += __shfl_xor_sync(0xffffffffu, a2, o);
        }
        if (tid == 0) {
            float mu  = a / (float)E_;
            float var = a2 / (float)E_ - mu * mu;
            ws[0]  = mu;
            ws2[0] = rsqrtf(var + 1e-5f);
        }
    }
    __syncthreads();
    float mu = ws[0], rstd = ws2[0];
    float4 gv = ((const float4*)g)[tid];
    float4 bv = ((const float4*)bt)[tid];
    __half2 h0 = __floats2half2_rn((v.x - mu) * rstd * gv.x + bv.x,
                                   (v.y - mu) * rstd * gv.y + bv.y);
    __half2 h1 = __floats2half2_rn((v.z - mu) * rstd * gv.z + bv.z,
                                   (v.w - mu) * rstd * gv.w + bv.w);
    uint2 u = make_uint2(*(uint32_t*)&h0, *(uint32_t*)&h1);
    *(uint2*)(out + (size_t)row * E_ + tid * 4) = u;
}

// ---------------- fp16 mma GEMM: 128x128 block, 4 warps (2x2), 64x64 warp tile ----
// BK=32 (two k16 steps per stage), 4-stage cp.async. Row stride 40 halfs (20 words).
#define BK      32
#define SSTH    40                      // halfs per row
#define STAGE_HALFS (128 * SSTH)        // 5120 halfs = 10240 B
#define GSMEM_BYTES (4 * STAGE_HALFS * 2 * 2)

__global__ void __launch_bounds__(128, 2)
gemm_f16(const __half* __restrict__ A, const __half* __restrict__ W,
         const float* __restrict__ bias, const float* __restrict__ res,
         float* __restrict__ C, __half* __restrict__ Ch,
         int M, int Nn, int K, int relu) {
    extern __shared__ __half smemh[];
    __half* SA = smemh;
    __half* SB = smemh + 4 * STAGE_HALFS;
    uint32_t sa_u = (uint32_t)__cvta_generic_to_shared(SA);
    uint32_t sb_u = (uint32_t)__cvta_generic_to_shared(SB);

    int tid = threadIdx.x;
    int wid = tid >> 5, lane = tid & 31;
    int g = lane >> 2, t = lane & 3;
    int wm = wid >> 1, wn = wid & 1;
    int bm = blockIdx.y * 128, bn = blockIdx.x * 128;

    // loader: row = (tid>>2) + 32i, chunk = (tid&3) -> 16B = 8 halfs
    int lrow = tid >> 2, lc = tid & 3;
    const __half* Ag = A + (size_t)(bm + lrow) * K + lc * 8;
    const __half* Wg = W + (size_t)(bn + lrow) * K + lc * 8;
    uint32_t soff = (uint32_t)(lrow * SSTH * 2 + lc * 16);

    float acc[4][8][4];
    #pragma unroll
    for (int i = 0; i < 4; i++)
        #pragma unroll
        for (int j = 0; j < 8; j++)
            #pragma unroll
            for (int v = 0; v < 4; v++) acc[i][j][v] = 0.f;

    int S = K / BK;

    auto issue = [&](int s) {
        int st = s & 3;
        int koff = s * BK;
        uint32_t sbase = (uint32_t)(st * STAGE_HALFS * 2) + soff;
        #pragma unroll
        for (int i = 0; i < 4; i++) {
            cp16(sa_u + sbase + i * 32 * SSTH * 2, Ag + (size_t)i * 32 * K + koff);
            cp16(sb_u + sbase + i * 32 * SSTH * 2, Wg + (size_t)i * 32 * K + koff);
        }
        CP_COMMIT();
    };

    issue(0); issue(1); issue(2);

    for (int s = 0; s < S; s++) {
        CP_WAIT2();
        __syncthreads();
        if (s + 3 < S) issue(s + 3);
        else CP_COMMIT();

        int st = s & 3;
        const uint32_t* sa = (const uint32_t*)(SA + st * STAGE_HALFS);
        const uint32_t* sb = (const uint32_t*)(SB + st * STAGE_HALFS);
        #pragma unroll
        for (int ks = 0; ks < 2; ks++) {
            int ko = ks * 8 + t;         // half2-word index within the 20-word row
            uint32_t af[4][4];
            #pragma unroll
            for (int mi = 0; mi < 4; mi++) {
                int r0 = wm * 64 + mi * 16 + g;
                af[mi][0] = sa[r0 * 20 + ko];
                af[mi][1] = sa[(r0 + 8) * 20 + ko];
                af[mi][2] = sa[r0 * 20 + ko + 4];
                af[mi][3] = sa[(r0 + 8) * 20 + ko + 4];
            }
            uint32_t bf[8][2];
            #pragma unroll
            for (int ni = 0; ni < 8; ni++) {
                int rn = wn * 64 + ni * 8 + g;
                bf[ni][0] = sb[rn * 20 + ko];
                bf[ni][1] = sb[rn * 20 + ko + 4];
            }
            #pragma unroll
            for (int mi = 0; mi < 4; mi++)
                #pragma unroll
                for (int ni = 0; ni < 8; ni++)
                    mma_f16(acc[mi][ni], af[mi], bf[ni]);
        }
    }

    #pragma unroll
    for (int mi = 0; mi < 4; mi++) {
        int r0 = bm + wm * 64 + mi * 16 + g;
        #pragma unroll
        for (int half_ = 0; half_ < 2; half_++) {
            int row = r0 + half_ * 8;
            const float* rrow = res ? res + (size_t)row * Nn + bn + wn * 64 : nullptr;
            const float* brow = bias + bn + wn * 64;
            #pragma unroll
            for (int ni = 0; ni < 8; ni++) {
                int col = ni * 8 + 2 * t;
                float v0 = acc[mi][ni][half_ * 2 + 0] + brow[col];
                float v1 = acc[mi][ni][half_ * 2 + 1] + brow[col + 1];
                if (relu) { v0 = fmaxf(v0, 0.f); v1 = fmaxf(v1, 0.f); }
                if (rrow) { v0 += rrow[col]; v1 += rrow[col + 1]; }
                if (Ch) {
                    __half2 h = __floats2half2_rn(v0, v1);
                    *(uint32_t*)(Ch + (size_t)row * Nn + bn + wn * 64 + col) =
                        *(uint32_t*)&h;
                } else {
                    *(float2*)(C + (size_t)row * Nn + bn + wn * 64 + col) =
                        make_float2(v0, v1);
                }
            }
        }
    }
}

// ---------------- Tensor-core windowed attention (tf32, emits fp16 o) --------
#define KST 68
#define VST 72
#define KR_ELTS (32 * KST)
#define VR_ELTS (32 * VST)
#define ASMEM_BYTES ((2 * KR_ELTS + 2 * VR_ELTS + 128 * 36) * 4)

__global__ void __launch_bounds__(256)
attn_kernel(const float* __restrict__ qkv, const float* __restrict__ rel_pos,
            __half* __restrict__ o) {
    extern __shared__ float asmem[];
    float* Kr = asmem;
    float* Vr = asmem + 2 * KR_ELTS;
    uint32_t* Ps = (uint32_t*)(asmem + 2 * KR_ELTS + 2 * VR_ELTS);
    uint32_t kr_u = (uint32_t)__cvta_generic_to_shared(Kr);
    uint32_t vr_u = (uint32_t)__cvta_generic_to_shared(Vr);

    int tid = threadIdx.x;
    int wid = tid >> 5, lane = tid & 31;
    int g = lane >> 2, t = lane & 3;
    int b = blockIdx.z, h = blockIdx.y;
    int qs = blockIdx.x * 128;
    const float* base = qkv + (size_t)b * N_ * 3 * E_;
    const float* rp = rel_pos + h * MAXLEN;

    int row0 = qs + wid * 16 + g;
    uint32_t qf[8][4];
    {
        const float* q0 = base + (size_t)row0 * 3 * E_ + h * DH;
        const float* q1 = q0 + (size_t)8 * 3 * E_;
        #pragma unroll
        for (int kk = 0; kk < 8; kk++) {
            qf[kk][0] = cvt_tf32(0.125f * q0[kk * 8 + t]);
            qf[kk][1] = cvt_tf32(0.125f * q1[kk * 8 + t]);
            qf[kk][2] = cvt_tf32(0.125f * q0[kk * 8 + t + 4]);
            qf[kk][3] = cvt_tf32(0.125f * q1[kk * 8 + t + 4]);
        }
    }

    float oacc[8][4];
    #pragma unroll
    for (int i = 0; i < 8; i++)
        #pragma unroll
        for (int v = 0; v < 4; v++) oacc[i][v] = 0.f;
    float m_o[2] = {-INFINITY, -INFINITY};
    float lac[2] = {0.f, 0.f};

    int kt_lo = max(0, qs - (MAXLEN - 1)) >> 5;
    int kt_hi = (qs + 127) >> 5;

    int jrow = tid >> 3;
    int d0 = (tid & 7) * 8;
    const float* kgbase = base + E_ + h * DH + d0;
    const float* vgbase = base + 2 * E_ + h * DH + d0;

    auto issueKV = [&](int kt, int buf) {
        int ks0 = kt * 32;
        const float* kp = kgbase + (size_t)(ks0 + jrow) * 3 * E_;
        const float* vp = vgbase + (size_t)(ks0 + jrow) * 3 * E_;
        uint32_t kd = kr_u + (uint32_t)((buf * KR_ELTS + jrow * KST + d0) * 4);
        uint32_t vd = vr_u + (uint32_t)((buf * VR_ELTS + jrow * VST + d0) * 4);
        cp16(kd, kp); cp16(kd + 16, kp + 4);
        cp16(vd, vp); cp16(vd + 16, vp + 4);
        CP_COMMIT();
    };

    issueKV(kt_lo, 0);

    for (int kt = kt_lo; kt <= kt_hi; kt++) {
        int buf = (kt - kt_lo) & 1;
        __syncthreads();
        if (kt + 1 <= kt_hi) issueKV(kt + 1, buf ^ 1);
        else CP_COMMIT();
        CP_WAIT1();
        __syncthreads();

        const float* Kb = Kr + buf * KR_ELTS;
        const float* Vb = Vr + buf * VR_ELTS;
        int ks0 = kt * 32;

        float sacc[4][4];
        #pragma unroll
        for (int ni = 0; ni < 4; ni++)
            #pragma unroll
            for (int v = 0; v < 4; v++) sacc[ni][v] = 0.f;
        #pragma unroll
        for (int kk = 0; kk < 8; kk++) {
            uint32_t bf[4][2];
            #pragma unroll
            for (int ni = 0; ni < 4; ni++) {
                int rn = ni * 8 + g;
                bf[ni][0] = cvt_tf32(Kb[rn * KST + kk * 8 + t]);
                bf[ni][1] = cvt_tf32(Kb[rn * KST + kk * 8 + t + 4]);
            }
            #pragma unroll
            for (int ni = 0; ni < 4; ni++)
                mma_tf32(sacc[ni], qf[kk], bf[ni]);
        }

        float m_t[2] = {-INFINITY, -INFINITY};
        #pragma unroll
        for (int ni = 0; ni < 4; ni++) {
            #pragma unroll
            for (int v = 0; v < 4; v++) {
                int r = v >> 1;
                int i_glob = row0 + r * 8;
                int j = ks0 + ni * 8 + 2 * t + (v & 1);
                int rel = i_glob - j;
                float val;
                if (rel >= 0 && rel < MAXLEN) val = sacc[ni][v] + __ldg(rp + rel);
                else                          val = -INFINITY;
                sacc[ni][v] = val;
                m_t[r] = fmaxf(m_t[r], val);
            }
        }
        #pragma unroll
        for (int r = 0; r < 2; r++) {
            m_t[r] = fmaxf(m_t[r], __shfl_xor_sync(0xffffffffu, m_t[r], 1));
            m_t[r] = fmaxf(m_t[r], __shfl_xor_sync(0xffffffffu, m_t[r], 2));
        }
        float fac[2], m_n[2];
        #pragma unroll
        for (int r = 0; r < 2; r++) {
            m_n[r] = fmaxf(m_o[r], m_t[r]);
            fac[r] = (m_n[r] == -INFINITY) ? 1.f : __expf(m_o[r] - m_n[r]);
            if (m_o[r] == -INFINITY) fac[r] = 0.f;
            if (m_n[r] == -INFINITY) fac[r] = 1.f;
        }
        float psum[2] = {0.f, 0.f};
        int lrow0 = wid * 16 + g;
        #pragma unroll
        for (int ni = 0; ni < 4; ni++) {
            #pragma unroll
            for (int v = 0; v < 4; v++) {
                int r = v >> 1;
                float p = (m_n[r] == -INFINITY) ? 0.f : __expf(sacc[ni][v] - m_n[r]);
                psum[r] += p;
                Ps[(lrow0 + r * 8) * 36 + ni * 8 + 2 * t + (v & 1)] = cvt_tf32(p);
            }
        }
        #pragma unroll
        for (int r = 0; r < 2; r++) {
            psum[r] += __shfl_xor_sync(0xffffffffu, psum[r], 1);
            psum[r] += __shfl_xor_sync(0xffffffffu, psum[r], 2);
            lac[r] = lac[r] * fac[r] + psum[r];
            m_o[r] = m_n[r];
        }
        #pragma unroll
        for (int i = 0; i < 8; i++) {
            oacc[i][0] *= fac[0]; oacc[i][1] *= fac[0];
            oacc[i][2] *= fac[1]; oacc[i][3] *= fac[1];
        }
        __syncwarp();

        #pragma unroll
        for (int kk = 0; kk < 4; kk++) {
            uint32_t af[4];
            af[0] = Ps[lrow0 * 36 + kk * 8 + t];
            af[1] = Ps[(lrow0 + 8) * 36 + kk * 8 + t];
            af[2] = Ps[lrow0 * 36 + kk * 8 + t + 4];
            af[3] = Ps[(lrow0 + 8) * 36 + kk * 8 + t + 4];
            #pragma unroll
            for (int ni = 0; ni < 8; ni++) {
                uint32_t bf[2];
                bf[0] = cvt_tf32(Vb[(kk * 8 + t) * VST + ni * 8 + g]);
                bf[1] = cvt_tf32(Vb[(kk * 8 + t + 4) * VST + ni * 8 + g]);
                mma_tf32(oacc[ni], af, bf);
            }
        }
        __syncwarp();
    }

    float inv0 = 1.f / lac[0];
    float inv1 = 1.f / lac[1];
    __half* op0 = o + ((size_t)(b * N_) + row0) * E_ + h * DH;
    __half* op1 = op0 + (size_t)8 * E_;
    #pragma unroll
    for (int ni = 0; ni < 8; ni++) {
        int col = ni * 8 + 2 * t;
        __half2 h0 = __floats2half2_rn(oacc[ni][0] * inv0, oacc[ni][1] * inv0);
        __half2 h1 = __floats2half2_rn(oacc[ni][2] * inv1, oacc[ni][3] * inv1);
        *(uint32_t*)(op0 + col) = *(uint32_t*)&h0;
        *(uint32_t*)(op1 + col) = *(uint32_t*)&h1;
    }
}

// ---------------- driver ----------------
extern "C" void kernel_launch(void* const* d_in, const int* in_sizes, int n_in,
                              void* d_out, int out_size) {
    const float* x         = (const float*)d_in[0];
    const float* rel_pos   = (const float*)d_in[1];
    const float* in_proj_w = (const float*)d_in[2];
    const float* in_proj_b = (const float*)d_in[3];
    const float* out_w     = (const float*)d_in[4];
    const float* out_b     = (const float*)d_in[5];
    const float* w1        = (const float*)d_in[6];
    const float* b1        = (const float*)d_in[7];
    const float* w2        = (const float*)d_in[8];
    const float* b2        = (const float*)d_in[9];
    const float* ln1_g     = (const float*)d_in[10];
    const float* ln1_b     = (const float*)d_in[11];
    const float* ln2_g     = (const float*)d_in[12];
    const float* ln2_b     = (const float*)d_in[13];
    float* out = (float*)d_out;

    float *qkv;
    __half *xn, *o, *xm, *hbuf, *wqkv, *wout, *w1h, *w2h;
    cudaGetSymbolAddress((void**)&xn,   g_xn);
    cudaGetSymbolAddress((void**)&qkv,  g_qkv);
    cudaGetSymbolAddress((void**)&o,    g_o);
    cudaGetSymbolAddress((void**)&xm,   g_xm);
    cudaGetSymbolAddress((void**)&hbuf, g_hbuf);
    cudaGetSymbolAddress((void**)&wqkv, g_wqkv);
    cudaGetSymbolAddress((void**)&wout, g_wout);
    cudaGetSymbolAddress((void**)&w1h,  g_w1);
    cudaGetSymbolAddress((void**)&w2h,  g_w2);

    cudaFuncSetAttribute(gemm_f16, cudaFuncAttributeMaxDynamicSharedMemorySize,
                         GSMEM_BYTES);
    cudaFuncSetAttribute(attn_kernel, cudaFuncAttributeMaxDynamicSharedMemorySize,
                         ASMEM_BYTES);

    // weight conversion fp32 -> fp16 (rn)
    cvt_half_kernel<<<3 * E_ * E_ / 1024, 256>>>(in_proj_w, wqkv);
    cvt_half_kernel<<<E_ * E_ / 1024, 256>>>(out_w, wout);
    cvt_half_kernel<<<FF * E_ / 1024, 256>>>(w1, w1h);
    cvt_half_kernel<<<E_ * FF / 1024, 256>>>(w2, w2h);

    // 1) LN1 -> fp16
    ln_kernel<<<ROWS, 256>>>(x, ln1_g, ln1_b, xn);
    // 2) QKV (fp16 x fp16 -> fp32)
    gemm_f16<<<dim3(3 * E_ / 128, ROWS / 128), 128, GSMEM_BYTES>>>(
        xn, wqkv, in_proj_b, nullptr, qkv, nullptr, ROWS, 3 * E_, E_, 0);
    // 3) attention -> fp16 o
    attn_kernel<<<dim3(N_ / 128, H_, B_), 256, ASMEM_BYTES>>>(qkv, rel_pos, o);
    // 4) out = x + o @ wout^T + b (fp32 out)
    gemm_f16<<<dim3(E_ / 128, ROWS / 128), 128, GSMEM_BYTES>>>(
        o, wout, out_b, x, out, nullptr, ROWS, E_, E_, 0);
    // 5) LN2 -> fp16
    ln_kernel<<<ROWS, 256>>>(out, ln2_g, ln2_b, xm);
    // 6) h = relu(xm @ w1^T + b1) -> fp16
    gemm_f16<<<dim3(FF / 128, ROWS / 128), 128, GSMEM_BYTES>>>(
        xm, w1h, b1, nullptr, nullptr, hbuf, ROWS, FF, E_, 1);
    // 7) out += h @ w2^T + b2 (fp32 out)
    gemm_f16<<<dim3(E_ / 128, ROWS / 128), 128, GSMEM_BYTES>>>(
        hbuf, w2h, b2, out, out, nullptr, ROWS, E_, FF, 0);
}

// round 11
// speedup vs baseline: 1.9154x; 1.1879x over previous
#include <cuda_runtime.h>
#include <cuda_fp16.h>
#include <math.h>
#include <stdint.h>

#define E_    1024
#define H_    16
#define DH    64
#define B_    4
#define N_    1024
#define ROWS  (B_ * N_)      // 4096
#define FF    (4 * E_)       // 4096
#define MAXLEN 512

// ---------------- scratch (no allocs allowed) ----------------
__device__ __half g_xn[ROWS * E_];
__device__ float  g_qkv[ROWS * 3 * E_];
__device__ __half g_o[ROWS * E_];
__device__ __half g_xm[ROWS * E_];
__device__ __half g_hbuf[ROWS * FF];
__device__ __half g_wqkv[3 * E_ * E_];
__device__ __half g_wout[E_ * E_];
__device__ __half g_w1[FF * E_];
__device__ __half g_w2[E_ * FF];

__device__ __forceinline__ uint32_t cvt_tf32(float f) {
    uint32_t r;
    asm("cvt.rna.tf32.f32 %0, %1;" : "=r"(r) : "f"(f));
    return r;
}

__device__ __forceinline__ void mma_tf32(float* c, const uint32_t* a, const uint32_t* b) {
    asm volatile(
        "mma.sync.aligned.m16n8k8.row.col.f32.tf32.tf32.f32 "
        "{%0,%1,%2,%3}, {%4,%5,%6,%7}, {%8,%9}, {%0,%1,%2,%3};"
        : "+f"(c[0]), "+f"(c[1]), "+f"(c[2]), "+f"(c[3])
        : "r"(a[0]), "r"(a[1]), "r"(a[2]), "r"(a[3]), "r"(b[0]), "r"(b[1]));
}

__device__ __forceinline__ void mma_f16(float* c, const uint32_t* a, const uint32_t* b) {
    asm volatile(
        "mma.sync.aligned.m16n8k16.row.col.f32.f16.f16.f32 "
        "{%0,%1,%2,%3}, {%4,%5,%6,%7}, {%8,%9}, {%0,%1,%2,%3};"
        : "+f"(c[0]), "+f"(c[1]), "+f"(c[2]), "+f"(c[3])
        : "r"(a[0]), "r"(a[1]), "r"(a[2]), "r"(a[3]), "r"(b[0]), "r"(b[1]));
}

__device__ __forceinline__ void ldm_x4(uint32_t* r, uint32_t addr) {
    asm volatile("ldmatrix.sync.aligned.m8n8.x4.shared.b16 {%0,%1,%2,%3}, [%4];"
                 : "=r"(r[0]), "=r"(r[1]), "=r"(r[2]), "=r"(r[3]) : "r"(addr));
}

__device__ __forceinline__ void cp16(uint32_t smem_addr, const void* gptr) {
    asm volatile("cp.async.cg.shared.global [%0], [%1], 16;"
                 :: "r"(smem_addr), "l"(gptr) : "memory");
}
#define CP_COMMIT() asm volatile("cp.async.commit_group;" ::: "memory")
#define CP_WAIT2()  asm volatile("cp.async.wait_group 2;" ::: "memory")
#define CP_WAIT1()  asm volatile("cp.async.wait_group 1;" ::: "memory")

// ---------------- weight conversion fp32 -> fp16 ----------------
__global__ void cvt_half_kernel(const float* __restrict__ in, __half* __restrict__ out) {
    int i = (blockIdx.x * blockDim.x + threadIdx.x) * 4;
    float4 v = *(const float4*)(in + i);
    __half2 h0 = __floats2half2_rn(v.x, v.y);
    __half2 h1 = __floats2half2_rn(v.z, v.w);
    uint2 u = make_uint2(*(uint32_t*)&h0, *(uint32_t*)&h1);
    *(uint2*)(out + i) = u;
}

// ---------------- LayerNorm (emits fp16) ----------------
__global__ void ln_kernel(const float* __restrict__ x, const float* __restrict__ g,
                          const float* __restrict__ bt, __half* __restrict__ out) {
    int row = blockIdx.x;
    int tid = threadIdx.x;
    const float4* xr = (const float4*)(x + (size_t)row * E_);
    float4 v = xr[tid];
    float s  = v.x + v.y + v.z + v.w;
    float s2 = v.x*v.x + v.y*v.y + v.z*v.z + v.w*v.w;
    #pragma unroll
    for (int o = 16; o; o >>= 1) {
        s  += __shfl_xor_sync(0xffffffffu, s,  o);
        s2 += __shfl_xor_sync(0xffffffffu, s2, o);
    }
    __shared__ float ws[8], ws2[8];
    int w = tid >> 5;
    if ((tid & 31) == 0) { ws[w] = s; ws2[w] = s2; }
    __syncthreads();
    if (tid < 32) {
        float a  = (tid < 8) ? ws[tid]  : 0.f;
        float a2 = (tid < 8) ? ws2[tid] : 0.f;
        #pragma unroll
        for (int o = 4; o; o >>= 1) {
            a  += __shfl_xor_sync(0xffffffffu, a,  o);
            a2 += __shfl_xor_sync(0xffffffffu, a2, o);
        }
        if (tid == 0) {
            float mu  = a / (float)E_;
            float var = a2 / (float)E_ - mu * mu;
            ws[0]  = mu;
            ws2[0] = rsqrtf(var + 1e-5f);
        }
    }
    __syncthreads();
    float mu = ws[0], rstd = ws2[0];
    float4 gv = ((const float4*)g)[tid];
    float4 bv = ((const float4*)bt)[tid];
    __half2 h0 = __floats2half2_rn((v.x - mu) * rstd * gv.x + bv.x,
                                   (v.y - mu) * rstd * gv.y + bv.y);
    __half2 h1 = __floats2half2_rn((v.z - mu) * rstd * gv.z + bv.z,
                                   (v.w - mu) * rstd * gv.w + bv.w);
    uint2 u = make_uint2(*(uint32_t*)&h0, *(uint32_t*)&h1);
    *(uint2*)(out + (size_t)row * E_ + tid * 4) = u;
}

// ---------------- fp16 mma GEMM with ldmatrix fragment loads ----------------
#define BK      32
#define SSTH    40                      // halfs per row (20 words; conflict-free)
#define STAGE_HALFS (128 * SSTH)
#define GSMEM_BYTES (4 * STAGE_HALFS * 2 * 2)

__global__ void __launch_bounds__(128, 2)
gemm_f16(const __half* __restrict__ A, const __half* __restrict__ W,
         const float* __restrict__ bias, const float* __restrict__ res,
         float* __restrict__ C, __half* __restrict__ Ch,
         int M, int Nn, int K, int relu) {
    extern __shared__ __half smemh[];
    __half* SA = smemh;
    __half* SB = smemh + 4 * STAGE_HALFS;
    uint32_t sa_u = (uint32_t)__cvta_generic_to_shared(SA);
    uint32_t sb_u = (uint32_t)__cvta_generic_to_shared(SB);

    int tid = threadIdx.x;
    int wid = tid >> 5, lane = tid & 31;
    int g = lane >> 2, t = lane & 3;
    int wm = wid >> 1, wn = wid & 1;
    int bm = blockIdx.y * 128, bn = blockIdx.x * 128;

    int lrow = tid >> 2, lc = tid & 3;
    const __half* Ag = A + (size_t)(bm + lrow) * K + lc * 8;
    const __half* Wg = W + (size_t)(bn + lrow) * K + lc * 8;
    uint32_t soff = (uint32_t)(lrow * SSTH * 2 + lc * 16);

    // ldmatrix per-lane offsets (in halfs)
    int arow = (lane & 7) + ((lane >> 3) & 1) * 8;   // row within 16-row tile
    int acol = (lane >> 4) * 8;                      // k offset 0 or 8
    int brow = (lane & 7) + (lane >> 4) * 8;         // n-row within ni pair
    int bcol = ((lane >> 3) & 1) * 8;                // k offset 0 or 8

    float acc[4][8][4];
    #pragma unroll
    for (int i = 0; i < 4; i++)
        #pragma unroll
        for (int j = 0; j < 8; j++)
            #pragma unroll
            for (int v = 0; v < 4; v++) acc[i][j][v] = 0.f;

    int S = K / BK;

    auto issue = [&](int s) {
        int st = s & 3;
        int koff = s * BK;
        uint32_t sbase = (uint32_t)(st * STAGE_HALFS * 2) + soff;
        #pragma unroll
        for (int i = 0; i < 4; i++) {
            cp16(sa_u + sbase + i * 32 * SSTH * 2, Ag + (size_t)i * 32 * K + koff);
            cp16(sb_u + sbase + i * 32 * SSTH * 2, Wg + (size_t)i * 32 * K + koff);
        }
        CP_COMMIT();
    };

    issue(0); issue(1); issue(2);

    for (int s = 0; s < S; s++) {
        CP_WAIT2();
        __syncthreads();
        if (s + 3 < S) issue(s + 3);
        else CP_COMMIT();

        int st = s & 3;
        uint32_t sa_st = sa_u + (uint32_t)(st * STAGE_HALFS * 2);
        uint32_t sb_st = sb_u + (uint32_t)(st * STAGE_HALFS * 2);
        #pragma unroll
        for (int ks = 0; ks < 2; ks++) {
            int k0 = ks * 16;
            uint32_t af[4][4];
            #pragma unroll
            for (int mi = 0; mi < 4; mi++) {
                int r0 = wm * 64 + mi * 16;
                ldm_x4(af[mi], sa_st + (uint32_t)(((r0 + arow) * SSTH + k0 + acol) * 2));
            }
            uint32_t bf[8][2];
            #pragma unroll
            for (int np = 0; np < 4; np++) {      // ni pairs
                int n0 = wn * 64 + np * 16;
                uint32_t br[4];
                ldm_x4(br, sb_st + (uint32_t)(((n0 + brow) * SSTH + k0 + bcol) * 2));
                bf[np * 2 + 0][0] = br[0]; bf[np * 2 + 0][1] = br[1];
                bf[np * 2 + 1][0] = br[2]; bf[np * 2 + 1][1] = br[3];
            }
            #pragma unroll
            for (int mi = 0; mi < 4; mi++)
                #pragma unroll
                for (int ni = 0; ni < 8; ni++)
                    mma_f16(acc[mi][ni], af[mi], bf[ni]);
        }
    }

    #pragma unroll
    for (int mi = 0; mi < 4; mi++) {
        int r0 = bm + wm * 64 + mi * 16 + g;
        #pragma unroll
        for (int half_ = 0; half_ < 2; half_++) {
            int row = r0 + half_ * 8;
            const float* rrow = res ? res + (size_t)row * Nn + bn + wn * 64 : nullptr;
            const float* brow_ = bias + bn + wn * 64;
            #pragma unroll
            for (int ni = 0; ni < 8; ni++) {
                int col = ni * 8 + 2 * t;
                float v0 = acc[mi][ni][half_ * 2 + 0] + brow_[col];
                float v1 = acc[mi][ni][half_ * 2 + 1] + brow_[col + 1];
                if (relu) { v0 = fmaxf(v0, 0.f); v1 = fmaxf(v1, 0.f); }
                if (rrow) { v0 += rrow[col]; v1 += rrow[col + 1]; }
                if (Ch) {
                    __half2 h = __floats2half2_rn(v0, v1);
                    *(uint32_t*)(Ch + (size_t)row * Nn + bn + wn * 64 + col) =
                        *(uint32_t*)&h;
                } else {
                    *(float2*)(C + (size_t)row * Nn + bn + wn * 64 + col) =
                        make_float2(v0, v1);
                }
            }
        }
    }
}

// ---------------- Tensor-core windowed attention (tf32, emits fp16 o) --------
#define KST 68
#define VST 72
#define KR_ELTS (32 * KST)
#define VR_ELTS (32 * VST)
#define ASMEM_BYTES ((2 * KR_ELTS + 2 * VR_ELTS + 128 * 36) * 4)

__global__ void __launch_bounds__(256)
attn_kernel(const float* __restrict__ qkv, const float* __restrict__ rel_pos,
            __half* __restrict__ o) {
    extern __shared__ float asmem[];
    float* Kr = asmem;
    float* Vr = asmem + 2 * KR_ELTS;
    uint32_t* Ps = (uint32_t*)(asmem + 2 * KR_ELTS + 2 * VR_ELTS);
    uint32_t kr_u = (uint32_t)__cvta_generic_to_shared(Kr);
    uint32_t vr_u = (uint32_t)__cvta_generic_to_shared(Vr);

    int tid = threadIdx.x;
    int wid = tid >> 5, lane = tid & 31;
    int g = lane >> 2, t = lane & 3;
    int b = blockIdx.z, h = blockIdx.y;
    int qs = blockIdx.x * 128;
    const float* base = qkv + (size_t)b * N_ * 3 * E_;
    const float* rp = rel_pos + h * MAXLEN;

    int row0 = qs + wid * 16 + g;
    uint32_t qf[8][4];
    {
        const float* q0 = base + (size_t)row0 * 3 * E_ + h * DH;
        const float* q1 = q0 + (size_t)8 * 3 * E_;
        #pragma unroll
        for (int kk = 0; kk < 8; kk++) {
            qf[kk][0] = cvt_tf32(0.125f * q0[kk * 8 + t]);
            qf[kk][1] = cvt_tf32(0.125f * q1[kk * 8 + t]);
            qf[kk][2] = cvt_tf32(0.125f * q0[kk * 8 + t + 4]);
            qf[kk][3] = cvt_tf32(0.125f * q1[kk * 8 + t + 4]);
        }
    }

    float oacc[8][4];
    #pragma unroll
    for (int i = 0; i < 8; i++)
        #pragma unroll
        for (int v = 0; v < 4; v++) oacc[i][v] = 0.f;
    float m_o[2] = {-INFINITY, -INFINITY};
    float lac[2] = {0.f, 0.f};

    int kt_lo = max(0, qs - (MAXLEN - 1)) >> 5;
    int kt_hi = (qs + 127) >> 5;

    int jrow = tid >> 3;
    int d0 = (tid & 7) * 8;
    const float* kgbase = base + E_ + h * DH + d0;
    const float* vgbase = base + 2 * E_ + h * DH + d0;

    auto issueKV = [&](int kt, int buf) {
        int ks0 = kt * 32;
        const float* kp = kgbase + (size_t)(ks0 + jrow) * 3 * E_;
        const float* vp = vgbase + (size_t)(ks0 + jrow) * 3 * E_;
        uint32_t kd = kr_u + (uint32_t)((buf * KR_ELTS + jrow * KST + d0) * 4);
        uint32_t vd = vr_u + (uint32_t)((buf * VR_ELTS + jrow * VST + d0) * 4);
        cp16(kd, kp); cp16(kd + 16, kp + 4);
        cp16(vd, vp); cp16(vd + 16, vp + 4);
        CP_COMMIT();
    };

    issueKV(kt_lo, 0);

    for (int kt = kt_lo; kt <= kt_hi; kt++) {
        int buf = (kt - kt_lo) & 1;
        __syncthreads();
        if (kt + 1 <= kt_hi) issueKV(kt + 1, buf ^ 1);
        else CP_COMMIT();
        CP_WAIT1();
        __syncthreads();

        const float* Kb = Kr + buf * KR_ELTS;
        const float* Vb = Vr + buf * VR_ELTS;
        int ks0 = kt * 32;

        float sacc[4][4];
        #pragma unroll
        for (int ni = 0; ni < 4; ni++)
            #pragma unroll
            for (int v = 0; v < 4; v++) sacc[ni][v] = 0.f;
        #pragma unroll
        for (int kk = 0; kk < 8; kk++) {
            uint32_t bf[4][2];
            #pragma unroll
            for (int ni = 0; ni < 4; ni++) {
                int rn = ni * 8 + g;
                bf[ni][0] = cvt_tf32(Kb[rn * KST + kk * 8 + t]);
                bf[ni][1] = cvt_tf32(Kb[rn * KST + kk * 8 + t + 4]);
            }
            #pragma unroll
            for (int ni = 0; ni < 4; ni++)
                mma_tf32(sacc[ni], qf[kk], bf[ni]);
        }

        float m_t[2] = {-INFINITY, -INFINITY};
        #pragma unroll
        for (int ni = 0; ni < 4; ni++) {
            #pragma unroll
            for (int v = 0; v < 4; v++) {
                int r = v >> 1;
                int i_glob = row0 + r * 8;
                int j = ks0 + ni * 8 + 2 * t + (v & 1);
                int rel = i_glob - j;
                float val;
                if (rel >= 0 && rel < MAXLEN) val = sacc[ni][v] + __ldg(rp + rel);
                else                          val = -INFINITY;
                sacc[ni][v] = val;
                m_t[r] = fmaxf(m_t[r], val);
            }
        }
        #pragma unroll
        for (int r = 0; r < 2; r++) {
            m_t[r] = fmaxf(m_t[r], __shfl_xor_sync(0xffffffffu, m_t[r], 1));
            m_t[r] = fmaxf(m_t[r], __shfl_xor_sync(0xffffffffu, m_t[r], 2));
        }
        float fac[2], m_n[2];
        #pragma unroll
        for (int r = 0; r < 2; r++) {
            m_n[r] = fmaxf(m_o[r], m_t[r]);
            fac[r] = (m_n[r] == -INFINITY) ? 1.f : __expf(m_o[r] - m_n[r]);
            if (m_o[r] == -INFINITY) fac[r] = 0.f;
            if (m_n[r] == -INFINITY) fac[r] = 1.f;
        }
        float psum[2] = {0.f, 0.f};
        int lrow0 = wid * 16 + g;
        #pragma unroll
        for (int ni = 0; ni < 4; ni++) {
            #pragma unroll
            for (int v = 0; v < 4; v++) {
                int r = v >> 1;
                float p = (m_n[r] == -INFINITY) ? 0.f : __expf(sacc[ni][v] - m_n[r]);
                psum[r] += p;
                Ps[(lrow0 + r * 8) * 36 + ni * 8 + 2 * t + (v & 1)] = cvt_tf32(p);
            }
        }
        #pragma unroll
        for (int r = 0; r < 2; r++) {
            psum[r] += __shfl_xor_sync(0xffffffffu, psum[r], 1);
            psum[r] += __shfl_xor_sync(0xffffffffu, psum[r], 2);
            lac[r] = lac[r] * fac[r] + psum[r];
            m_o[r] = m_n[r];
        }
        #pragma unroll
        for (int i = 0; i < 8; i++) {
            oacc[i][0] *= fac[0]; oacc[i][1] *= fac[0];
            oacc[i][2] *= fac[1]; oacc[i][3] *= fac[1];
        }
        __syncwarp();

        #pragma unroll
        for (int kk = 0; kk < 4; kk++) {
            uint32_t af[4];
            af[0] = Ps[lrow0 * 36 + kk * 8 + t];
            af[1] = Ps[(lrow0 + 8) * 36 + kk * 8 + t];
            af[2] = Ps[lrow0 * 36 + kk * 8 + t + 4];
            af[3] = Ps[(lrow0 + 8) * 36 + kk * 8 + t + 4];
            #pragma unroll
            for (int ni = 0; ni < 8; ni++) {
                uint32_t bf[2];
                bf[0] = cvt_tf32(Vb[(kk * 8 + t) * VST + ni * 8 + g]);
                bf[1] = cvt_tf32(Vb[(kk * 8 + t + 4) * VST + ni * 8 + g]);
                mma_tf32(oacc[ni], af, bf);
            }
        }
        __syncwarp();
    }

    float inv0 = 1.f / lac[0];
    float inv1 = 1.f / lac[1];
    __half* op0 = o + ((size_t)(b * N_) + row0) * E_ + h * DH;
    __half* op1 = op0 + (size_t)8 * E_;
    #pragma unroll
    for (int ni = 0; ni < 8; ni++) {
        int col = ni * 8 + 2 * t;
        __half2 h0 = __floats2half2_rn(oacc[ni][0] * inv0, oacc[ni][1] * inv0);
        __half2 h1 = __floats2half2_rn(oacc[ni][2] * inv1, oacc[ni][3] * inv1);
        *(uint32_t*)(op0 + col) = *(uint32_t*)&h0;
        *(uint32_t*)(op1 + col) = *(uint32_t*)&h1;
    }
}

// ---------------- driver ----------------
extern "C" void kernel_launch(void* const* d_in, const int* in_sizes, int n_in,
                              void* d_out, int out_size) {
    const float* x         = (const float*)d_in[0];
    const float* rel_pos   = (const float*)d_in[1];
    const float* in_proj_w = (const float*)d_in[2];
    const float* in_proj_b = (const float*)d_in[3];
    const float* out_w     = (const float*)d_in[4];
    const float* out_b     = (const float*)d_in[5];
    const float* w1        = (const float*)d_in[6];
    const float* b1        = (const float*)d_in[7];
    const float* w2        = (const float*)d_in[8];
    const float* b2        = (const float*)d_in[9];
    const float* ln1_g     = (const float*)d_in[10];
    const float* ln1_b     = (const float*)d_in[11];
    const float* ln2_g     = (const float*)d_in[12];
    const float* ln2_b     = (const float*)d_in[13];
    float* out = (float*)d_out;

    float *qkv;
    __half *xn, *o, *xm, *hbuf, *wqkv, *wout, *w1h, *w2h;
    cudaGetSymbolAddress((void**)&xn,   g_xn);
    cudaGetSymbolAddress((void**)&qkv,  g_qkv);
    cudaGetSymbolAddress((void**)&o,    g_o);
    cudaGetSymbolAddress((void**)&xm,   g_xm);
    cudaGetSymbolAddress((void**)&hbuf, g_hbuf);
    cudaGetSymbolAddress((void**)&wqkv, g_wqkv);
    cudaGetSymbolAddress((void**)&wout, g_wout);
    cudaGetSymbolAddress((void**)&w1h,  g_w1);
    cudaGetSymbolAddress((void**)&w2h,  g_w2);

    cudaFuncSetAttribute(gemm_f16, cudaFuncAttributeMaxDynamicSharedMemorySize,
                         GSMEM_BYTES);
    cudaFuncSetAttribute(attn_kernel, cudaFuncAttributeMaxDynamicSharedMemorySize,
                         ASMEM_BYTES);

    cvt_half_kernel<<<3 * E_ * E_ / 1024, 256>>>(in_proj_w, wqkv);
    cvt_half_kernel<<<E_ * E_ / 1024, 256>>>(out_w, wout);
    cvt_half_kernel<<<FF * E_ / 1024, 256>>>(w1, w1h);
    cvt_half_kernel<<<E_ * FF / 1024, 256>>>(w2, w2h);

    ln_kernel<<<ROWS, 256>>>(x, ln1_g, ln1_b, xn);
    gemm_f16<<<dim3(3 * E_ / 128, ROWS / 128), 128, GSMEM_BYTES>>>(
        xn, wqkv, in_proj_b, nullptr, qkv, nullptr, ROWS, 3 * E_, E_, 0);
    attn_kernel<<<dim3(N_ / 128, H_, B_), 256, ASMEM_BYTES>>>(qkv, rel_pos, o);
    gemm_f16<<<dim3(E_ / 128, ROWS / 128), 128, GSMEM_BYTES>>>(
        o, wout, out_b, x, out, nullptr, ROWS, E_, E_, 0);
    ln_kernel<<<ROWS, 256>>>(out, ln2_g, ln2_b, xm);
    gemm_f16<<<dim3(FF / 128, ROWS / 128), 128, GSMEM_BYTES>>>(
        xm, w1h, b1, nullptr, nullptr, hbuf, ROWS, FF, E_, 1);
    gemm_f16<<<dim3(E_ / 128, ROWS / 128), 128, GSMEM_BYTES>>>(
        hbuf, w2h, b2, out, out, nullptr, ROWS, E_, FF, 0);
}

// round 12
// speedup vs baseline: 2.1651x; 1.1303x over previous
#include <cuda_runtime.h>
#include <cuda_fp16.h>
#include <math.h>
#include <stdint.h>

#define E_    1024
#define H_    16
#define DH    64
#define B_    4
#define N_    1024
#define ROWS  (B_ * N_)      // 4096
#define FF    (4 * E_)       // 4096
#define MAXLEN 512

// ---------------- scratch (no allocs allowed) ----------------
__device__ __half g_xn[ROWS * E_];
__device__ __half g_qkv[ROWS * 3 * E_];   // fp16 now
__device__ __half g_o[ROWS * E_];
__device__ __half g_xm[ROWS * E_];
__device__ __half g_hbuf[ROWS * FF];
__device__ __half g_wqkv[3 * E_ * E_];
__device__ __half g_wout[E_ * E_];
__device__ __half g_w1[FF * E_];
__device__ __half g_w2[E_ * FF];

__device__ __forceinline__ void mma_f16(float* c, const uint32_t* a, const uint32_t* b) {
    asm volatile(
        "mma.sync.aligned.m16n8k16.row.col.f32.f16.f16.f32 "
        "{%0,%1,%2,%3}, {%4,%5,%6,%7}, {%8,%9}, {%0,%1,%2,%3};"
        : "+f"(c[0]), "+f"(c[1]), "+f"(c[2]), "+f"(c[3])
        : "r"(a[0]), "r"(a[1]), "r"(a[2]), "r"(a[3]), "r"(b[0]), "r"(b[1]));
}

__device__ __forceinline__ void ldm_x4(uint32_t* r, uint32_t addr) {
    asm volatile("ldmatrix.sync.aligned.m8n8.x4.shared.b16 {%0,%1,%2,%3}, [%4];"
                 : "=r"(r[0]), "=r"(r[1]), "=r"(r[2]), "=r"(r[3]) : "r"(addr));
}
__device__ __forceinline__ void ldm_x4t(uint32_t* r, uint32_t addr) {
    asm volatile("ldmatrix.sync.aligned.m8n8.x4.trans.shared.b16 {%0,%1,%2,%3}, [%4];"
                 : "=r"(r[0]), "=r"(r[1]), "=r"(r[2]), "=r"(r[3]) : "r"(addr));
}

__device__ __forceinline__ void cp16(uint32_t smem_addr, const void* gptr) {
    asm volatile("cp.async.cg.shared.global [%0], [%1], 16;"
                 :: "r"(smem_addr), "l"(gptr) : "memory");
}
#define CP_COMMIT() asm volatile("cp.async.commit_group;" ::: "memory")
#define CP_WAIT2()  asm volatile("cp.async.wait_group 2;" ::: "memory")
#define CP_WAIT1()  asm volatile("cp.async.wait_group 1;" ::: "memory")

// ---------------- fused weight conversion fp32 -> fp16 ----------------
__global__ void cvt_all_kernel(const float* __restrict__ a, const float* __restrict__ b,
                               const float* __restrict__ c, const float* __restrict__ d,
                               __half* __restrict__ oa, __half* __restrict__ ob,
                               __half* __restrict__ oc, __half* __restrict__ od) {
    const int Q1 = 3 * E_ * E_ / 4;
    const int Q2 = Q1 + E_ * E_ / 4;
    const int Q3 = Q2 + FF * E_ / 4;
    int i = blockIdx.x * blockDim.x + threadIdx.x;
    const float* src; __half* dst; int off;
    if (i < Q1)      { src = a; dst = oa; off = i; }
    else if (i < Q2) { src = b; dst = ob; off = i - Q1; }
    else if (i < Q3) { src = c; dst = oc; off = i - Q2; }
    else             { src = d; dst = od; off = i - Q3; }
    float4 v = ((const float4*)src)[off];
    __half2 h0 = __floats2half2_rn(v.x, v.y);
    __half2 h1 = __floats2half2_rn(v.z, v.w);
    uint2 u = make_uint2(*(uint32_t*)&h0, *(uint32_t*)&h1);
    ((uint2*)dst)[off] = u;
}

// ---------------- LayerNorm (emits fp16) ----------------
__global__ void ln_kernel(const float* __restrict__ x, const float* __restrict__ g,
                          const float* __restrict__ bt, __half* __restrict__ out) {
    int row = blockIdx.x;
    int tid = threadIdx.x;
    const float4* xr = (const float4*)(x + (size_t)row * E_);
    float4 v = xr[tid];
    float s  = v.x + v.y + v.z + v.w;
    float s2 = v.x*v.x + v.y*v.y + v.z*v.z + v.w*v.w;
    #pragma unroll
    for (int o = 16; o; o >>= 1) {
        s  += __shfl_xor_sync(0xffffffffu, s,  o);
        s2 += __shfl_xor_sync(0xffffffffu, s2, o);
    }
    __shared__ float ws[8], ws2[8];
    int w = tid >> 5;
    if ((tid & 31) == 0) { ws[w] = s; ws2[w] = s2; }
    __syncthreads();
    if (tid < 32) {
        float a  = (tid < 8) ? ws[tid]  : 0.f;
        float a2 = (tid < 8) ? ws2[tid] : 0.f;
        #pragma unroll
        for (int o = 4; o; o >>= 1) {
            a  += __shfl_xor_sync(0xffffffffu, a,  o);
            a2 += __shfl_xor_sync(0xffffffffu, a2, o);
        }
        if (tid == 0) {
            float mu  = a / (float)E_;
            float var = a2 / (float)E_ - mu * mu;
            ws[0]  = mu;
            ws2[0] = rsqrtf(var + 1e-5f);
        }
    }
    __syncthreads();
    float mu = ws[0], rstd = ws2[0];
    float4 gv = ((const float4*)g)[tid];
    float4 bv = ((const float4*)bt)[tid];
    __half2 h0 = __floats2half2_rn((v.x - mu) * rstd * gv.x + bv.x,
                                   (v.y - mu) * rstd * gv.y + bv.y);
    __half2 h1 = __floats2half2_rn((v.z - mu) * rstd * gv.z + bv.z,
                                   (v.w - mu) * rstd * gv.w + bv.w);
    uint2 u = make_uint2(*(uint32_t*)&h0, *(uint32_t*)&h1);
    *(uint2*)(out + (size_t)row * E_ + tid * 4) = u;
}

// ---------------- fp16 mma GEMM with ldmatrix (round-11 proven) ----------------
#define BK      32
#define SSTH    40
#define STAGE_HALFS (128 * SSTH)
#define GSMEM_BYTES (4 * STAGE_HALFS * 2 * 2)

__global__ void __launch_bounds__(128, 2)
gemm_f16(const __half* __restrict__ A, const __half* __restrict__ W,
         const float* __restrict__ bias, const float* __restrict__ res,
         float* __restrict__ C, __half* __restrict__ Ch,
         int M, int Nn, int K, int relu) {
    extern __shared__ __half smemh[];
    __half* SA = smemh;
    __half* SB = smemh + 4 * STAGE_HALFS;
    uint32_t sa_u = (uint32_t)__cvta_generic_to_shared(SA);
    uint32_t sb_u = (uint32_t)__cvta_generic_to_shared(SB);

    int tid = threadIdx.x;
    int wid = tid >> 5, lane = tid & 31;
    int g = lane >> 2, t = lane & 3;
    int wm = wid >> 1, wn = wid & 1;
    int bm = blockIdx.y * 128, bn = blockIdx.x * 128;

    int lrow = tid >> 2, lc = tid & 3;
    const __half* Ag = A + (size_t)(bm + lrow) * K + lc * 8;
    const __half* Wg = W + (size_t)(bn + lrow) * K + lc * 8;
    uint32_t soff = (uint32_t)(lrow * SSTH * 2 + lc * 16);

    int arow = (lane & 7) + ((lane >> 3) & 1) * 8;
    int acol = (lane >> 4) * 8;
    int brow = (lane & 7) + (lane >> 4) * 8;
    int bcol = ((lane >> 3) & 1) * 8;

    float acc[4][8][4];
    #pragma unroll
    for (int i = 0; i < 4; i++)
        #pragma unroll
        for (int j = 0; j < 8; j++)
            #pragma unroll
            for (int v = 0; v < 4; v++) acc[i][j][v] = 0.f;

    int S = K / BK;

    auto issue = [&](int s) {
        int st = s & 3;
        int koff = s * BK;
        uint32_t sbase = (uint32_t)(st * STAGE_HALFS * 2) + soff;
        #pragma unroll
        for (int i = 0; i < 4; i++) {
            cp16(sa_u + sbase + i * 32 * SSTH * 2, Ag + (size_t)i * 32 * K + koff);
            cp16(sb_u + sbase + i * 32 * SSTH * 2, Wg + (size_t)i * 32 * K + koff);
        }
        CP_COMMIT();
    };

    issue(0); issue(1); issue(2);

    for (int s = 0; s < S; s++) {
        CP_WAIT2();
        __syncthreads();
        if (s + 3 < S) issue(s + 3);
        else CP_COMMIT();

        int st = s & 3;
        uint32_t sa_st = sa_u + (uint32_t)(st * STAGE_HALFS * 2);
        uint32_t sb_st = sb_u + (uint32_t)(st * STAGE_HALFS * 2);
        #pragma unroll
        for (int ks = 0; ks < 2; ks++) {
            int k0 = ks * 16;
            uint32_t af[4][4];
            #pragma unroll
            for (int mi = 0; mi < 4; mi++) {
                int r0 = wm * 64 + mi * 16;
                ldm_x4(af[mi], sa_st + (uint32_t)(((r0 + arow) * SSTH + k0 + acol) * 2));
            }
            uint32_t bf[8][2];
            #pragma unroll
            for (int np = 0; np < 4; np++) {
                int n0 = wn * 64 + np * 16;
                uint32_t br[4];
                ldm_x4(br, sb_st + (uint32_t)(((n0 + brow) * SSTH + k0 + bcol) * 2));
                bf[np * 2 + 0][0] = br[0]; bf[np * 2 + 0][1] = br[1];
                bf[np * 2 + 1][0] = br[2]; bf[np * 2 + 1][1] = br[3];
            }
            #pragma unroll
            for (int mi = 0; mi < 4; mi++)
                #pragma unroll
                for (int ni = 0; ni < 8; ni++)
                    mma_f16(acc[mi][ni], af[mi], bf[ni]);
        }
    }

    #pragma unroll
    for (int mi = 0; mi < 4; mi++) {
        int r0 = bm + wm * 64 + mi * 16 + g;
        #pragma unroll
        for (int half_ = 0; half_ < 2; half_++) {
            int row = r0 + half_ * 8;
            const float* rrow = res ? res + (size_t)row * Nn + bn + wn * 64 : nullptr;
            const float* brow_ = bias + bn + wn * 64;
            #pragma unroll
            for (int ni = 0; ni < 8; ni++) {
                int col = ni * 8 + 2 * t;
                float v0 = acc[mi][ni][half_ * 2 + 0] + brow_[col];
                float v1 = acc[mi][ni][half_ * 2 + 1] + brow_[col + 1];
                if (relu) { v0 = fmaxf(v0, 0.f); v1 = fmaxf(v1, 0.f); }
                if (rrow) { v0 += rrow[col]; v1 += rrow[col + 1]; }
                if (Ch) {
                    __half2 hh = __floats2half2_rn(v0, v1);
                    *(uint32_t*)(Ch + (size_t)row * Nn + bn + wn * 64 + col) =
                        *(uint32_t*)&hh;
                } else {
                    *(float2*)(C + (size_t)row * Nn + bn + wn * 64 + col) =
                        make_float2(v0, v1);
                }
            }
        }
    }
}

// ---------------- fp16 tensor-core windowed attention ----------------
// smem (halfs): Kh[2][32][72] | Vh[2][32][72] | Ps[128][40]
#define AKST 72
#define APST 40
#define AK_ELTS (32 * AKST)
#define ASMEM_BYTES ((4 * AK_ELTS + 128 * APST) * 2)

__global__ void __launch_bounds__(256)
attn_kernel(const __half* __restrict__ qkv, const float* __restrict__ rel_pos,
            __half* __restrict__ o) {
    extern __shared__ __half ash[];
    __half* Kh = ash;
    __half* Vh = ash + 2 * AK_ELTS;
    __half* Ps = ash + 4 * AK_ELTS;
    uint32_t kh_u = (uint32_t)__cvta_generic_to_shared(Kh);
    uint32_t vh_u = (uint32_t)__cvta_generic_to_shared(Vh);
    uint32_t ps_u = (uint32_t)__cvta_generic_to_shared(Ps);

    int tid = threadIdx.x;
    int wid = tid >> 5, lane = tid & 31;
    int g = lane >> 2, t = lane & 3;
    int b = blockIdx.z, h = blockIdx.y;
    int qs = blockIdx.x * 128;
    const __half* base = qkv + (size_t)b * N_ * 3 * E_;
    const float* rp = rel_pos + h * MAXLEN;

    int row0 = qs + wid * 16 + g;
    // Q fragments fp16 (unscaled; scale applied post-mma)
    uint32_t qf[4][4];
    {
        const __half* q0 = base + (size_t)row0 * 3 * E_ + h * DH;
        const __half* q1 = q0 + (size_t)8 * 3 * E_;
        #pragma unroll
        for (int kk = 0; kk < 4; kk++) {
            qf[kk][0] = *(const uint32_t*)(q0 + kk * 16 + 2 * t);
            qf[kk][1] = *(const uint32_t*)(q1 + kk * 16 + 2 * t);
            qf[kk][2] = *(const uint32_t*)(q0 + kk * 16 + 8 + 2 * t);
            qf[kk][3] = *(const uint32_t*)(q1 + kk * 16 + 8 + 2 * t);
        }
    }

    float oacc[8][4];
    #pragma unroll
    for (int i = 0; i < 8; i++)
        #pragma unroll
        for (int v = 0; v < 4; v++) oacc[i][v] = 0.f;
    float m_o[2] = {-INFINITY, -INFINITY};
    float lac[2] = {0.f, 0.f};

    int kt_lo = max(0, qs - (MAXLEN - 1)) >> 5;
    int kt_hi = (qs + 127) >> 5;

    int jrow = tid >> 3;          // 0..31 key row
    int jc = (tid & 7) * 8;       // halfs offset within row (8 chunks of 8 halfs)
    const __half* kgbase = base + E_ + h * DH + jc;
    const __half* vgbase = base + 2 * E_ + h * DH + jc;

    auto issueKV = [&](int kt, int buf) {
        int ks0 = kt * 32;
        cp16(kh_u + (uint32_t)((buf * AK_ELTS + jrow * AKST + jc) * 2),
             kgbase + (size_t)(ks0 + jrow) * 3 * E_);
        cp16(vh_u + (uint32_t)((buf * AK_ELTS + jrow * AKST + jc) * 2),
             vgbase + (size_t)(ks0 + jrow) * 3 * E_);
        CP_COMMIT();
    };

    issueKV(kt_lo, 0);

    int brow = (lane & 7) + (lane >> 4) * 8;
    int bcol = ((lane >> 3) & 1) * 8;
    int arow = (lane & 7) + ((lane >> 3) & 1) * 8;
    int acol = (lane >> 4) * 8;
    int vdg = (lane >> 4) & 1;          // d-group within pair
    int vkg = (lane >> 3) & 1;          // key-word group
    int vrr = lane & 7;

    for (int kt = kt_lo; kt <= kt_hi; kt++) {
        int buf = (kt - kt_lo) & 1;
        __syncthreads();
        if (kt + 1 <= kt_hi) issueKV(kt + 1, buf ^ 1);
        else CP_COMMIT();
        CP_WAIT1();
        __syncthreads();

        uint32_t kb = kh_u + (uint32_t)(buf * AK_ELTS * 2);
        uint32_t vb = vh_u + (uint32_t)(buf * AK_ELTS * 2);
        int ks0 = kt * 32;

        // ---- S = Q K^T (fp16, fp32 accum) ----
        float sacc[4][4];
        #pragma unroll
        for (int ni = 0; ni < 4; ni++)
            #pragma unroll
            for (int v = 0; v < 4; v++) sacc[ni][v] = 0.f;
        #pragma unroll
        for (int kk = 0; kk < 4; kk++) {
            int k0 = kk * 16;
            uint32_t bf[4][2];
            #pragma unroll
            for (int np = 0; np < 2; np++) {
                uint32_t br[4];
                ldm_x4(br, kb + (uint32_t)(((np * 16 + brow) * AKST + k0 + bcol) * 2));
                bf[np * 2 + 0][0] = br[0]; bf[np * 2 + 0][1] = br[1];
                bf[np * 2 + 1][0] = br[2]; bf[np * 2 + 1][1] = br[3];
            }
            #pragma unroll
            for (int ni = 0; ni < 4; ni++)
                mma_f16(sacc[ni], qf[kk], bf[ni]);
        }

        // ---- scale + bias + mask + online softmax ----
        float m_t[2] = {-INFINITY, -INFINITY};
        #pragma unroll
        for (int ni = 0; ni < 4; ni++) {
            #pragma unroll
            for (int v = 0; v < 4; v++) {
                int r = v >> 1;
                int i_glob = row0 + r * 8;
                int j = ks0 + ni * 8 + 2 * t + (v & 1);
                int rel = i_glob - j;
                float val;
                if (rel >= 0 && rel < MAXLEN)
                    val = sacc[ni][v] * 0.125f + __ldg(rp + rel);
                else
                    val = -INFINITY;
                sacc[ni][v] = val;
                m_t[r] = fmaxf(m_t[r], val);
            }
        }
        #pragma unroll
        for (int r = 0; r < 2; r++) {
            m_t[r] = fmaxf(m_t[r], __shfl_xor_sync(0xffffffffu, m_t[r], 1));
            m_t[r] = fmaxf(m_t[r], __shfl_xor_sync(0xffffffffu, m_t[r], 2));
        }
        float fac[2], m_n[2];
        #pragma unroll
        for (int r = 0; r < 2; r++) {
            m_n[r] = fmaxf(m_o[r], m_t[r]);
            fac[r] = (m_n[r] == -INFINITY) ? 1.f : __expf(m_o[r] - m_n[r]);
            if (m_o[r] == -INFINITY) fac[r] = 0.f;
            if (m_n[r] == -INFINITY) fac[r] = 1.f;
        }
        float psum[2] = {0.f, 0.f};
        int lrow0 = wid * 16 + g;
        #pragma unroll
        for (int ni = 0; ni < 4; ni++) {
            #pragma unroll
            for (int v = 0; v < 4; v++) {
                int r = v >> 1;
                float p = (m_n[r] == -INFINITY) ? 0.f : __expf(sacc[ni][v] - m_n[r]);
                psum[r] += p;
                Ps[(lrow0 + r * 8) * APST + ni * 8 + 2 * t + (v & 1)] = __float2half_rn(p);
            }
        }
        #pragma unroll
        for (int r = 0; r < 2; r++) {
            psum[r] += __shfl_xor_sync(0xffffffffu, psum[r], 1);
            psum[r] += __shfl_xor_sync(0xffffffffu, psum[r], 2);
            lac[r] = lac[r] * fac[r] + psum[r];
            m_o[r] = m_n[r];
        }
        #pragma unroll
        for (int i = 0; i < 8; i++) {
            oacc[i][0] *= fac[0]; oacc[i][1] *= fac[0];
            oacc[i][2] *= fac[1]; oacc[i][3] *= fac[1];
        }
        __syncwarp();

        // ---- O += P V (fp16) ----
        #pragma unroll
        for (int kk = 0; kk < 2; kk++) {
            int k0 = kk * 16;
            uint32_t af[4];
            ldm_x4(af, ps_u + (uint32_t)(((wid * 16 + arow) * APST + k0 + acol) * 2));
            #pragma unroll
            for (int np = 0; np < 4; np++) {
                uint32_t br[4];
                ldm_x4t(br, vb + (uint32_t)(((k0 + vkg * 8 + vrr) * AKST
                                             + np * 16 + vdg * 8) * 2));
                uint32_t b0[2] = {br[0], br[1]};
                uint32_t b1[2] = {br[2], br[3]};
                mma_f16(oacc[np * 2 + 0], af, b0);
                mma_f16(oacc[np * 2 + 1], af, b1);
            }
        }
        __syncwarp();
    }

    float inv0 = 1.f / lac[0];
    float inv1 = 1.f / lac[1];
    __half* op0 = o + ((size_t)(b * N_) + row0) * E_ + h * DH;
    __half* op1 = op0 + (size_t)8 * E_;
    #pragma unroll
    for (int ni = 0; ni < 8; ni++) {
        int col = ni * 8 + 2 * t;
        __half2 h0 = __floats2half2_rn(oacc[ni][0] * inv0, oacc[ni][1] * inv0);
        __half2 h1 = __floats2half2_rn(oacc[ni][2] * inv1, oacc[ni][3] * inv1);
        *(uint32_t*)(op0 + col) = *(uint32_t*)&h0;
        *(uint32_t*)(op1 + col) = *(uint32_t*)&h1;
    }
}

// ---------------- driver ----------------
extern "C" void kernel_launch(void* const* d_in, const int* in_sizes, int n_in,
                              void* d_out, int out_size) {
    const float* x         = (const float*)d_in[0];
    const float* rel_pos   = (const float*)d_in[1];
    const float* in_proj_w = (const float*)d_in[2];
    const float* in_proj_b = (const float*)d_in[3];
    const float* out_w     = (const float*)d_in[4];
    const float* out_b     = (const float*)d_in[5];
    const float* w1        = (const float*)d_in[6];
    const float* b1        = (const float*)d_in[7];
    const float* w2        = (const float*)d_in[8];
    const float* b2        = (const float*)d_in[9];
    const float* ln1_g     = (const float*)d_in[10];
    const float* ln1_b     = (const float*)d_in[11];
    const float* ln2_g     = (const float*)d_in[12];
    const float* ln2_b     = (const float*)d_in[13];
    float* out = (float*)d_out;

    __half *xn, *qkv, *o, *xm, *hbuf, *wqkv, *wout, *w1h, *w2h;
    cudaGetSymbolAddress((void**)&xn,   g_xn);
    cudaGetSymbolAddress((void**)&qkv,  g_qkv);
    cudaGetSymbolAddress((void**)&o,    g_o);
    cudaGetSymbolAddress((void**)&xm,   g_xm);
    cudaGetSymbolAddress((void**)&hbuf, g_hbuf);
    cudaGetSymbolAddress((void**)&wqkv, g_wqkv);
    cudaGetSymbolAddress((void**)&wout, g_wout);
    cudaGetSymbolAddress((void**)&w1h,  g_w1);
    cudaGetSymbolAddress((void**)&w2h,  g_w2);

    cudaFuncSetAttribute(gemm_f16, cudaFuncAttributeMaxDynamicSharedMemorySize,
                         GSMEM_BYTES);
    cudaFuncSetAttribute(attn_kernel, cudaFuncAttributeMaxDynamicSharedMemorySize,
                         ASMEM_BYTES);

    // fused weight conversion (12*E^2 elements total, 4 per thread)
    cvt_all_kernel<<<12 * E_ * E_ / 1024, 256>>>(in_proj_w, out_w, w1, w2,
                                                 wqkv, wout, w1h, w2h);

    ln_kernel<<<ROWS, 256>>>(x, ln1_g, ln1_b, xn);
    // QKV -> fp16
    gemm_f16<<<dim3(3 * E_ / 128, ROWS / 128), 128, GSMEM_BYTES>>>(
        xn, wqkv, in_proj_b, nullptr, nullptr, qkv, ROWS, 3 * E_, E_, 0);
    attn_kernel<<<dim3(N_ / 128, H_, B_), 256, ASMEM_BYTES>>>(qkv, rel_pos, o);
    gemm_f16<<<dim3(E_ / 128, ROWS / 128), 128, GSMEM_BYTES>>>(
        o, wout, out_b, x, out, nullptr, ROWS, E_, E_, 0);
    ln_kernel<<<ROWS, 256>>>(out, ln2_g, ln2_b, xm);
    gemm_f16<<<dim3(FF / 128, ROWS / 128), 128, GSMEM_BYTES>>>(
        xm, w1h, b1, nullptr, nullptr, hbuf, ROWS, FF, E_, 1);
    gemm_f16<<<dim3(E_ / 128, ROWS / 128), 128, GSMEM_BYTES>>>(
        hbuf, w2h, b2, out, out, nullptr, ROWS, E_, FF, 0);
}

// round 13
// speedup vs baseline: 2.1950x; 1.0138x over previous
#include <cuda_runtime.h>
#include <cuda_fp16.h>
#include <math.h>
#include <stdint.h>

#define E_    1024
#define H_    16
#define DH    64
#define B_    4
#define N_    1024
#define ROWS  (B_ * N_)      // 4096
#define FF    (4 * E_)       // 4096
#define MAXLEN 512

// ---------------- scratch (no allocs allowed) ----------------
__device__ __half g_xn[ROWS * E_];
__device__ __half g_qkv[ROWS * 3 * E_];
__device__ __half g_o[ROWS * E_];
__device__ __half g_xm[ROWS * E_];
__device__ __half g_hbuf[ROWS * FF];
__device__ __half g_wqkv[3 * E_ * E_];
__device__ __half g_wout[E_ * E_];
__device__ __half g_w1[FF * E_];
__device__ __half g_w2[E_ * FF];

__device__ __forceinline__ void mma_f16(float* c, const uint32_t* a, const uint32_t* b) {
    asm volatile(
        "mma.sync.aligned.m16n8k16.row.col.f32.f16.f16.f32 "
        "{%0,%1,%2,%3}, {%4,%5,%6,%7}, {%8,%9}, {%0,%1,%2,%3};"
        : "+f"(c[0]), "+f"(c[1]), "+f"(c[2]), "+f"(c[3])
        : "r"(a[0]), "r"(a[1]), "r"(a[2]), "r"(a[3]), "r"(b[0]), "r"(b[1]));
}

__device__ __forceinline__ void ldm_x4(uint32_t* r, uint32_t addr) {
    asm volatile("ldmatrix.sync.aligned.m8n8.x4.shared.b16 {%0,%1,%2,%3}, [%4];"
                 : "=r"(r[0]), "=r"(r[1]), "=r"(r[2]), "=r"(r[3]) : "r"(addr));
}
__device__ __forceinline__ void ldm_x4t(uint32_t* r, uint32_t addr) {
    asm volatile("ldmatrix.sync.aligned.m8n8.x4.trans.shared.b16 {%0,%1,%2,%3}, [%4];"
                 : "=r"(r[0]), "=r"(r[1]), "=r"(r[2]), "=r"(r[3]) : "r"(addr));
}

__device__ __forceinline__ void cp16(uint32_t smem_addr, const void* gptr) {
    asm volatile("cp.async.cg.shared.global [%0], [%1], 16;"
                 :: "r"(smem_addr), "l"(gptr) : "memory");
}
#define CP_COMMIT() asm volatile("cp.async.commit_group;" ::: "memory")
#define CP_WAIT2()  asm volatile("cp.async.wait_group 2;" ::: "memory")
#define CP_WAIT1()  asm volatile("cp.async.wait_group 1;" ::: "memory")

// ---------------- fused weight conversion fp32 -> fp16 ----------------
__global__ void cvt_all_kernel(const float* __restrict__ a, const float* __restrict__ b,
                               const float* __restrict__ c, const float* __restrict__ d,
                               __half* __restrict__ oa, __half* __restrict__ ob,
                               __half* __restrict__ oc, __half* __restrict__ od) {
    const int Q1 = 3 * E_ * E_ / 4;
    const int Q2 = Q1 + E_ * E_ / 4;
    const int Q3 = Q2 + FF * E_ / 4;
    int i = blockIdx.x * blockDim.x + threadIdx.x;
    const float* src; __half* dst; int off;
    if (i < Q1)      { src = a; dst = oa; off = i; }
    else if (i < Q2) { src = b; dst = ob; off = i - Q1; }
    else if (i < Q3) { src = c; dst = oc; off = i - Q2; }
    else             { src = d; dst = od; off = i - Q3; }
    float4 v = ((const float4*)src)[off];
    __half2 h0 = __floats2half2_rn(v.x, v.y);
    __half2 h1 = __floats2half2_rn(v.z, v.w);
    uint2 u = make_uint2(*(uint32_t*)&h0, *(uint32_t*)&h1);
    ((uint2*)dst)[off] = u;
}

// ---------------- LayerNorm (emits fp16) ----------------
__global__ void ln_kernel(const float* __restrict__ x, const float* __restrict__ g,
                          const float* __restrict__ bt, __half* __restrict__ out) {
    int row = blockIdx.x;
    int tid = threadIdx.x;
    const float4* xr = (const float4*)(x + (size_t)row * E_);
    float4 v = xr[tid];
    float s  = v.x + v.y + v.z + v.w;
    float s2 = v.x*v.x + v.y*v.y + v.z*v.z + v.w*v.w;
    #pragma unroll
    for (int o = 16; o; o >>= 1) {
        s  += __shfl_xor_sync(0xffffffffu, s,  o);
        s2 += __shfl_xor_sync(0xffffffffu, s2, o);
    }
    __shared__ float ws[8], ws2[8];
    int w = tid >> 5;
    if ((tid & 31) == 0) { ws[w] = s; ws2[w] = s2; }
    __syncthreads();
    if (tid < 32) {
        float a  = (tid < 8) ? ws[tid]  : 0.f;
        float a2 = (tid < 8) ? ws2[tid] : 0.f;
        #pragma unroll
        for (int o = 4; o; o >>= 1) {
            a  += __shfl_xor_sync(0xffffffffu, a,  o);
            a2 += __shfl_xor_sync(0xffffffffu, a2, o);
        }
        if (tid == 0) {
            float mu  = a / (float)E_;
            float var = a2 / (float)E_ - mu * mu;
            ws[0]  = mu;
            ws2[0] = rsqrtf(var + 1e-5f);
        }
    }
    __syncthreads();
    float mu = ws[0], rstd = ws2[0];
    float4 gv = ((const float4*)g)[tid];
    float4 bv = ((const float4*)bt)[tid];
    __half2 h0 = __floats2half2_rn((v.x - mu) * rstd * gv.x + bv.x,
                                   (v.y - mu) * rstd * gv.y + bv.y);
    __half2 h1 = __floats2half2_rn((v.z - mu) * rstd * gv.z + bv.z,
                                   (v.w - mu) * rstd * gv.w + bv.w);
    uint2 u = make_uint2(*(uint32_t*)&h0, *(uint32_t*)&h1);
    *(uint2*)(out + (size_t)row * E_ + tid * 4) = u;
}

// ---------------- fp16 mma GEMM with ldmatrix (round-11 proven) ----------------
#define BK      32
#define SSTH    40
#define STAGE_HALFS (128 * SSTH)
#define GSMEM_BYTES (4 * STAGE_HALFS * 2 * 2)

__global__ void __launch_bounds__(128, 2)
gemm_f16(const __half* __restrict__ A, const __half* __restrict__ W,
         const float* __restrict__ bias, const float* __restrict__ res,
         float* __restrict__ C, __half* __restrict__ Ch,
         int M, int Nn, int K, int relu) {
    extern __shared__ __half smemh[];
    __half* SA = smemh;
    __half* SB = smemh + 4 * STAGE_HALFS;
    uint32_t sa_u = (uint32_t)__cvta_generic_to_shared(SA);
    uint32_t sb_u = (uint32_t)__cvta_generic_to_shared(SB);

    int tid = threadIdx.x;
    int wid = tid >> 5, lane = tid & 31;
    int g = lane >> 2, t = lane & 3;
    int wm = wid >> 1, wn = wid & 1;
    int bm = blockIdx.y * 128, bn = blockIdx.x * 128;

    int lrow = tid >> 2, lc = tid & 3;
    const __half* Ag = A + (size_t)(bm + lrow) * K + lc * 8;
    const __half* Wg = W + (size_t)(bn + lrow) * K + lc * 8;
    uint32_t soff = (uint32_t)(lrow * SSTH * 2 + lc * 16);

    int arow = (lane & 7) + ((lane >> 3) & 1) * 8;
    int acol = (lane >> 4) * 8;
    int brow = (lane & 7) + (lane >> 4) * 8;
    int bcol = ((lane >> 3) & 1) * 8;

    float acc[4][8][4];
    #pragma unroll
    for (int i = 0; i < 4; i++)
        #pragma unroll
        for (int j = 0; j < 8; j++)
            #pragma unroll
            for (int v = 0; v < 4; v++) acc[i][j][v] = 0.f;

    int S = K / BK;

    auto issue = [&](int s) {
        int st = s & 3;
        int koff = s * BK;
        uint32_t sbase = (uint32_t)(st * STAGE_HALFS * 2) + soff;
        #pragma unroll
        for (int i = 0; i < 4; i++) {
            cp16(sa_u + sbase + i * 32 * SSTH * 2, Ag + (size_t)i * 32 * K + koff);
            cp16(sb_u + sbase + i * 32 * SSTH * 2, Wg + (size_t)i * 32 * K + koff);
        }
        CP_COMMIT();
    };

    issue(0); issue(1); issue(2);

    for (int s = 0; s < S; s++) {
        CP_WAIT2();
        __syncthreads();
        if (s + 3 < S) issue(s + 3);
        else CP_COMMIT();

        int st = s & 3;
        uint32_t sa_st = sa_u + (uint32_t)(st * STAGE_HALFS * 2);
        uint32_t sb_st = sb_u + (uint32_t)(st * STAGE_HALFS * 2);
        #pragma unroll
        for (int ks = 0; ks < 2; ks++) {
            int k0 = ks * 16;
            uint32_t af[4][4];
            #pragma unroll
            for (int mi = 0; mi < 4; mi++) {
                int r0 = wm * 64 + mi * 16;
                ldm_x4(af[mi], sa_st + (uint32_t)(((r0 + arow) * SSTH + k0 + acol) * 2));
            }
            uint32_t bf[8][2];
            #pragma unroll
            for (int np = 0; np < 4; np++) {
                int n0 = wn * 64 + np * 16;
                uint32_t br[4];
                ldm_x4(br, sb_st + (uint32_t)(((n0 + brow) * SSTH + k0 + bcol) * 2));
                bf[np * 2 + 0][0] = br[0]; bf[np * 2 + 0][1] = br[1];
                bf[np * 2 + 1][0] = br[2]; bf[np * 2 + 1][1] = br[3];
            }
            #pragma unroll
            for (int mi = 0; mi < 4; mi++)
                #pragma unroll
                for (int ni = 0; ni < 8; ni++)
                    mma_f16(acc[mi][ni], af[mi], bf[ni]);
        }
    }

    #pragma unroll
    for (int mi = 0; mi < 4; mi++) {
        int r0 = bm + wm * 64 + mi * 16 + g;
        #pragma unroll
        for (int half_ = 0; half_ < 2; half_++) {
            int row = r0 + half_ * 8;
            const float* rrow = res ? res + (size_t)row * Nn + bn + wn * 64 : nullptr;
            const float* brow_ = bias + bn + wn * 64;
            #pragma unroll
            for (int ni = 0; ni < 8; ni++) {
                int col = ni * 8 + 2 * t;
                float v0 = acc[mi][ni][half_ * 2 + 0] + brow_[col];
                float v1 = acc[mi][ni][half_ * 2 + 1] + brow_[col + 1];
                if (relu) { v0 = fmaxf(v0, 0.f); v1 = fmaxf(v1, 0.f); }
                if (rrow) { v0 += rrow[col]; v1 += rrow[col + 1]; }
                if (Ch) {
                    __half2 hh = __floats2half2_rn(v0, v1);
                    *(uint32_t*)(Ch + (size_t)row * Nn + bn + wn * 64 + col) =
                        *(uint32_t*)&hh;
                } else {
                    *(float2*)(C + (size_t)row * Nn + bn + wn * 64 + col) =
                        make_float2(v0, v1);
                }
            }
        }
    }
}

// ---------------- fp16 tensor-core windowed attention, 64-key tiles ----------
// smem (halfs): Kh[2][64][72] | Vh[2][64][72] | Ps[128][72]
#define AKST 72
#define ATILE 64
#define AK_ELTS (ATILE * AKST)
#define ASMEM_BYTES ((4 * AK_ELTS + 128 * AKST) * 2)

__global__ void __launch_bounds__(256)
attn_kernel(const __half* __restrict__ qkv, const float* __restrict__ rel_pos,
            __half* __restrict__ o) {
    extern __shared__ __half ash[];
    __half* Kh = ash;
    __half* Vh = ash + 2 * AK_ELTS;
    __half* Ps = ash + 4 * AK_ELTS;
    uint32_t kh_u = (uint32_t)__cvta_generic_to_shared(Kh);
    uint32_t vh_u = (uint32_t)__cvta_generic_to_shared(Vh);
    uint32_t ps_u = (uint32_t)__cvta_generic_to_shared(Ps);

    int tid = threadIdx.x;
    int wid = tid >> 5, lane = tid & 31;
    int g = lane >> 2, t = lane & 3;
    int b = blockIdx.z, h = blockIdx.y;
    int qs = blockIdx.x * 128;
    const __half* base = qkv + (size_t)b * N_ * 3 * E_;
    const float* rp = rel_pos + h * MAXLEN;

    int row0 = qs + wid * 16 + g;
    int row_lo = qs + wid * 16;               // warp's first q row
    // Q fragments fp16 (unscaled; scale applied post-mma)
    uint32_t qf[4][4];
    {
        const __half* q0 = base + (size_t)row0 * 3 * E_ + h * DH;
        const __half* q1 = q0 + (size_t)8 * 3 * E_;
        #pragma unroll
        for (int kk = 0; kk < 4; kk++) {
            qf[kk][0] = *(const uint32_t*)(q0 + kk * 16 + 2 * t);
            qf[kk][1] = *(const uint32_t*)(q1 + kk * 16 + 2 * t);
            qf[kk][2] = *(const uint32_t*)(q0 + kk * 16 + 8 + 2 * t);
            qf[kk][3] = *(const uint32_t*)(q1 + kk * 16 + 8 + 2 * t);
        }
    }

    float oacc[8][4];
    #pragma unroll
    for (int i = 0; i < 8; i++)
        #pragma unroll
        for (int v = 0; v < 4; v++) oacc[i][v] = 0.f;
    float m_o[2] = {-INFINITY, -INFINITY};
    float lac[2] = {0.f, 0.f};

    int kt_lo = max(0, qs - (MAXLEN - 1)) >> 6;
    int kt_hi = (qs + 127) >> 6;

    // loader mapping: 4 threads per key row, 2 cp16 each (64 halfs/row)
    int jrow = tid >> 2;                // 0..63
    int jc = (tid & 3) * 16;            // halfs: 0,16,32,48
    const __half* kgbase = base + E_ + h * DH + jc;
    const __half* vgbase = base + 2 * E_ + h * DH + jc;

    auto issueKV = [&](int kt, int buf) {
        int ks0 = kt * ATILE;
        const __half* kp = kgbase + (size_t)(ks0 + jrow) * 3 * E_;
        const __half* vp = vgbase + (size_t)(ks0 + jrow) * 3 * E_;
        uint32_t kd = kh_u + (uint32_t)((buf * AK_ELTS + jrow * AKST + jc) * 2);
        uint32_t vd = vh_u + (uint32_t)((buf * AK_ELTS + jrow * AKST + jc) * 2);
        cp16(kd, kp); cp16(kd + 16, kp + 8);
        cp16(vd, vp); cp16(vd + 16, vp + 8);
        CP_COMMIT();
    };

    issueKV(kt_lo, 0);

    int brow = (lane & 7) + (lane >> 4) * 8;
    int bcol = ((lane >> 3) & 1) * 8;
    int arow = (lane & 7) + ((lane >> 3) & 1) * 8;
    int acol = (lane >> 4) * 8;
    int vdg = (lane >> 4) & 1;
    int vkg = (lane >> 3) & 1;
    int vrr = lane & 7;

    for (int kt = kt_lo; kt <= kt_hi; kt++) {
        int buf = (kt - kt_lo) & 1;
        __syncthreads();
        if (kt + 1 <= kt_hi) issueKV(kt + 1, buf ^ 1);
        else CP_COMMIT();
        CP_WAIT1();
        __syncthreads();

        int ks0 = kt * ATILE;
        // per-warp tile skip: keys needed in [row_lo-511, row_lo+15]
        if (ks0 > row_lo + 15 || ks0 + (ATILE - 1) < row_lo - (MAXLEN - 1))
            continue;

        uint32_t kb = kh_u + (uint32_t)(buf * AK_ELTS * 2);
        uint32_t vb = vh_u + (uint32_t)(buf * AK_ELTS * 2);

        // ---- S = Q K^T (16 x 64 per warp) ----
        float sacc[8][4];
        #pragma unroll
        for (int ni = 0; ni < 8; ni++)
            #pragma unroll
            for (int v = 0; v < 4; v++) sacc[ni][v] = 0.f;
        #pragma unroll
        for (int kk = 0; kk < 4; kk++) {
            int k0 = kk * 16;
            uint32_t bf[8][2];
            #pragma unroll
            for (int np = 0; np < 4; np++) {
                uint32_t br[4];
                ldm_x4(br, kb + (uint32_t)(((np * 16 + brow) * AKST + k0 + bcol) * 2));
                bf[np * 2 + 0][0] = br[0]; bf[np * 2 + 0][1] = br[1];
                bf[np * 2 + 1][0] = br[2]; bf[np * 2 + 1][1] = br[3];
            }
            #pragma unroll
            for (int ni = 0; ni < 8; ni++)
                mma_f16(sacc[ni], qf[kk], bf[ni]);
        }

        // ---- scale + bias + mask + online softmax ----
        float m_t[2] = {-INFINITY, -INFINITY};
        #pragma unroll
        for (int ni = 0; ni < 8; ni++) {
            #pragma unroll
            for (int v = 0; v < 4; v++) {
                int r = v >> 1;
                int i_glob = row0 + r * 8;
                int j = ks0 + ni * 8 + 2 * t + (v & 1);
                int rel = i_glob - j;
                float val;
                if (rel >= 0 && rel < MAXLEN)
                    val = sacc[ni][v] * 0.125f + __ldg(rp + rel);
                else
                    val = -INFINITY;
                sacc[ni][v] = val;
                m_t[r] = fmaxf(m_t[r], val);
            }
        }
        #pragma unroll
        for (int r = 0; r < 2; r++) {
            m_t[r] = fmaxf(m_t[r], __shfl_xor_sync(0xffffffffu, m_t[r], 1));
            m_t[r] = fmaxf(m_t[r], __shfl_xor_sync(0xffffffffu, m_t[r], 2));
        }
        float fac[2], m_n[2];
        #pragma unroll
        for (int r = 0; r < 2; r++) {
            m_n[r] = fmaxf(m_o[r], m_t[r]);
            fac[r] = (m_n[r] == -INFINITY) ? 1.f : __expf(m_o[r] - m_n[r]);
            if (m_o[r] == -INFINITY) fac[r] = 0.f;
            if (m_n[r] == -INFINITY) fac[r] = 1.f;
        }
        float psum[2] = {0.f, 0.f};
        int lrow0 = wid * 16 + g;
        #pragma unroll
        for (int ni = 0; ni < 8; ni++) {
            #pragma unroll
            for (int v = 0; v < 4; v++) {
                int r = v >> 1;
                float p = (m_n[r] == -INFINITY) ? 0.f : __expf(sacc[ni][v] - m_n[r]);
                psum[r] += p;
                Ps[(lrow0 + r * 8) * AKST + ni * 8 + 2 * t + (v & 1)] = __float2half_rn(p);
            }
        }
        #pragma unroll
        for (int r = 0; r < 2; r++) {
            psum[r] += __shfl_xor_sync(0xffffffffu, psum[r], 1);
            psum[r] += __shfl_xor_sync(0xffffffffu, psum[r], 2);
            lac[r] = lac[r] * fac[r] + psum[r];
            m_o[r] = m_n[r];
        }
        #pragma unroll
        for (int i = 0; i < 8; i++) {
            oacc[i][0] *= fac[0]; oacc[i][1] *= fac[0];
            oacc[i][2] *= fac[1]; oacc[i][3] *= fac[1];
        }
        __syncwarp();

        // ---- O += P V (k = 64) ----
        #pragma unroll
        for (int kk = 0; kk < 4; kk++) {
            int k0 = kk * 16;
            uint32_t af[4];
            ldm_x4(af, ps_u + (uint32_t)(((wid * 16 + arow) * AKST + k0 + acol) * 2));
            #pragma unroll
            for (int np = 0; np < 4; np++) {
                uint32_t br[4];
                ldm_x4t(br, vb + (uint32_t)(((k0 + vkg * 8 + vrr) * AKST
                                             + np * 16 + vdg * 8) * 2));
                uint32_t b0[2] = {br[0], br[1]};
                uint32_t b1[2] = {br[2], br[3]};
                mma_f16(oacc[np * 2 + 0], af, b0);
                mma_f16(oacc[np * 2 + 1], af, b1);
            }
        }
        __syncwarp();
    }

    float inv0 = 1.f / lac[0];
    float inv1 = 1.f / lac[1];
    __half* op0 = o + ((size_t)(b * N_) + row0) * E_ + h * DH;
    __half* op1 = op0 + (size_t)8 * E_;
    #pragma unroll
    for (int ni = 0; ni < 8; ni++) {
        int col = ni * 8 + 2 * t;
        __half2 h0 = __floats2half2_rn(oacc[ni][0] * inv0, oacc[ni][1] * inv0);
        __half2 h1 = __floats2half2_rn(oacc[ni][2] * inv1, oacc[ni][3] * inv1);
        *(uint32_t*)(op0 + col) = *(uint32_t*)&h0;
        *(uint32_t*)(op1 + col) = *(uint32_t*)&h1;
    }
}

// ---------------- driver ----------------
extern "C" void kernel_launch(void* const* d_in, const int* in_sizes, int n_in,
                              void* d_out, int out_size) {
    const float* x         = (const float*)d_in[0];
    const float* rel_pos   = (const float*)d_in[1];
    const float* in_proj_w = (const float*)d_in[2];
    const float* in_proj_b = (const float*)d_in[3];
    const float* out_w     = (const float*)d_in[4];
    const float* out_b     = (const float*)d_in[5];
    const float* w1        = (const float*)d_in[6];
    const float* b1        = (const float*)d_in[7];
    const float* w2        = (const float*)d_in[8];
    const float* b2        = (const float*)d_in[9];
    const float* ln1_g     = (const float*)d_in[10];
    const float* ln1_b     = (const float*)d_in[11];
    const float* ln2_g     = (const float*)d_in[12];
    const float* ln2_b     = (const float*)d_in[13];
    float* out = (float*)d_out;

    __half *xn, *qkv, *o, *xm, *hbuf, *wqkv, *wout, *w1h, *w2h;
    cudaGetSymbolAddress((void**)&xn,   g_xn);
    cudaGetSymbolAddress((void**)&qkv,  g_qkv);
    cudaGetSymbolAddress((void**)&o,    g_o);
    cudaGetSymbolAddress((void**)&xm,   g_xm);
    cudaGetSymbolAddress((void**)&hbuf, g_hbuf);
    cudaGetSymbolAddress((void**)&wqkv, g_wqkv);
    cudaGetSymbolAddress((void**)&wout, g_wout);
    cudaGetSymbolAddress((void**)&w1h,  g_w1);
    cudaGetSymbolAddress((void**)&w2h,  g_w2);

    cudaFuncSetAttribute(gemm_f16, cudaFuncAttributeMaxDynamicSharedMemorySize,
                         GSMEM_BYTES);
    cudaFuncSetAttribute(attn_kernel, cudaFuncAttributeMaxDynamicSharedMemorySize,
                         ASMEM_BYTES);

    cvt_all_kernel<<<12 * E_ * E_ / 1024, 256>>>(in_proj_w, out_w, w1, w2,
                                                 wqkv, wout, w1h, w2h);

    ln_kernel<<<ROWS, 256>>>(x, ln1_g, ln1_b, xn);
    gemm_f16<<<dim3(3 * E_ / 128, ROWS / 128), 128, GSMEM_BYTES>>>(
        xn, wqkv, in_proj_b, nullptr, nullptr, qkv, ROWS, 3 * E_, E_, 0);
    attn_kernel<<<dim3(N_ / 128, H_, B_), 256, ASMEM_BYTES>>>(qkv, rel_pos, o);
    gemm_f16<<<dim3(E_ / 128, ROWS / 128), 128, GSMEM_BYTES>>>(
        o, wout, out_b, x, out, nullptr, ROWS, E_, E_, 0);
    ln_kernel<<<ROWS, 256>>>(out, ln2_g, ln2_b, xm);
    gemm_f16<<<dim3(FF / 128, ROWS / 128), 128, GSMEM_BYTES>>>(
        xm, w1h, b1, nullptr, nullptr, hbuf, ROWS, FF, E_, 1);
    gemm_f16<<<dim3(E_ / 128, ROWS / 128), 128, GSMEM_BYTES>>>(
        hbuf, w2h, b2, out, out, nullptr, ROWS, E_, FF, 0);
}

// round 14
// speedup vs baseline: 2.2387x; 1.0199x over previous
#include <cuda_runtime.h>
#include <cuda_fp16.h>
#include <math.h>
#include <stdint.h>

#define E_    1024
#define H_    16
#define DH    64
#define B_    4
#define N_    1024
#define ROWS  (B_ * N_)      // 4096
#define FF    (4 * E_)       // 4096
#define MAXLEN 512

// ---------------- scratch (no allocs allowed) ----------------
__device__ __half g_xn[ROWS * E_];
__device__ __half g_qkv[ROWS * 3 * E_];
__device__ __half g_o[ROWS * E_];
__device__ __half g_xm[ROWS * E_];
__device__ __half g_hbuf[ROWS * FF];
__device__ __half g_wqkv[3 * E_ * E_];
__device__ __half g_wout[E_ * E_];
__device__ __half g_w1[FF * E_];
__device__ __half g_w2[E_ * FF];

__device__ __forceinline__ void mma_f16(float* c, const uint32_t* a, const uint32_t* b) {
    asm volatile(
        "mma.sync.aligned.m16n8k16.row.col.f32.f16.f16.f32 "
        "{%0,%1,%2,%3}, {%4,%5,%6,%7}, {%8,%9}, {%0,%1,%2,%3};"
        : "+f"(c[0]), "+f"(c[1]), "+f"(c[2]), "+f"(c[3])
        : "r"(a[0]), "r"(a[1]), "r"(a[2]), "r"(a[3]), "r"(b[0]), "r"(b[1]));
}

__device__ __forceinline__ void ldm_x4(uint32_t* r, uint32_t addr) {
    asm volatile("ldmatrix.sync.aligned.m8n8.x4.shared.b16 {%0,%1,%2,%3}, [%4];"
                 : "=r"(r[0]), "=r"(r[1]), "=r"(r[2]), "=r"(r[3]) : "r"(addr));
}
__device__ __forceinline__ void ldm_x4t(uint32_t* r, uint32_t addr) {
    asm volatile("ldmatrix.sync.aligned.m8n8.x4.trans.shared.b16 {%0,%1,%2,%3}, [%4];"
                 : "=r"(r[0]), "=r"(r[1]), "=r"(r[2]), "=r"(r[3]) : "r"(addr));
}

__device__ __forceinline__ void cp16(uint32_t smem_addr, const void* gptr) {
    asm volatile("cp.async.cg.shared.global [%0], [%1], 16;"
                 :: "r"(smem_addr), "l"(gptr) : "memory");
}
#define CP_COMMIT() asm volatile("cp.async.commit_group;" ::: "memory")
#define CP_WAIT2()  asm volatile("cp.async.wait_group 2;" ::: "memory")
#define CP_WAIT1()  asm volatile("cp.async.wait_group 1;" ::: "memory")

// ---------------- fused weight conversion fp32 -> fp16 ----------------
__global__ void cvt_all_kernel(const float* __restrict__ a, const float* __restrict__ b,
                               const float* __restrict__ c, const float* __restrict__ d,
                               __half* __restrict__ oa, __half* __restrict__ ob,
                               __half* __restrict__ oc, __half* __restrict__ od) {
    const int Q1 = 3 * E_ * E_ / 4;
    const int Q2 = Q1 + E_ * E_ / 4;
    const int Q3 = Q2 + FF * E_ / 4;
    int i = blockIdx.x * blockDim.x + threadIdx.x;
    const float* src; __half* dst; int off;
    if (i < Q1)      { src = a; dst = oa; off = i; }
    else if (i < Q2) { src = b; dst = ob; off = i - Q1; }
    else if (i < Q3) { src = c; dst = oc; off = i - Q2; }
    else             { src = d; dst = od; off = i - Q3; }
    float4 v = ((const float4*)src)[off];
    __half2 h0 = __floats2half2_rn(v.x, v.y);
    __half2 h1 = __floats2half2_rn(v.z, v.w);
    uint2 u = make_uint2(*(uint32_t*)&h0, *(uint32_t*)&h1);
    ((uint2*)dst)[off] = u;
}

// ---------------- LayerNorm (emits fp16) ----------------
__global__ void ln_kernel(const float* __restrict__ x, const float* __restrict__ g,
                          const float* __restrict__ bt, __half* __restrict__ out) {
    int row = blockIdx.x;
    int tid = threadIdx.x;
    const float4* xr = (const float4*)(x + (size_t)row * E_);
    float4 v = xr[tid];
    float s  = v.x + v.y + v.z + v.w;
    float s2 = v.x*v.x + v.y*v.y + v.z*v.z + v.w*v.w;
    #pragma unroll
    for (int o = 16; o; o >>= 1) {
        s  += __shfl_xor_sync(0xffffffffu, s,  o);
        s2 += __shfl_xor_sync(0xffffffffu, s2, o);
    }
    __shared__ float ws[8], ws2[8];
    int w = tid >> 5;
    if ((tid & 31) == 0) { ws[w] = s; ws2[w] = s2; }
    __syncthreads();
    if (tid < 32) {
        float a  = (tid < 8) ? ws[tid]  : 0.f;
        float a2 = (tid < 8) ? ws2[tid] : 0.f;
        #pragma unroll
        for (int o = 4; o; o >>= 1) {
            a  += __shfl_xor_sync(0xffffffffu, a,  o);
            a2 += __shfl_xor_sync(0xffffffffu, a2, o);
        }
        if (tid == 0) {
            float mu  = a / (float)E_;
            float var = a2 / (float)E_ - mu * mu;
            ws[0]  = mu;
            ws2[0] = rsqrtf(var + 1e-5f);
        }
    }
    __syncthreads();
    float mu = ws[0], rstd = ws2[0];
    float4 gv = ((const float4*)g)[tid];
    float4 bv = ((const float4*)bt)[tid];
    __half2 h0 = __floats2half2_rn((v.x - mu) * rstd * gv.x + bv.x,
                                   (v.y - mu) * rstd * gv.y + bv.y);
    __half2 h1 = __floats2half2_rn((v.z - mu) * rstd * gv.z + bv.z,
                                   (v.w - mu) * rstd * gv.w + bv.w);
    uint2 u = make_uint2(*(uint32_t*)&h0, *(uint32_t*)&h1);
    *(uint2*)(out + (size_t)row * E_ + tid * 4) = u;
}

// ---------------- fp16 mma GEMM with ldmatrix (round-11 proven) ----------------
#define BK      32
#define SSTH    40
#define STAGE_HALFS (128 * SSTH)
#define GSMEM_BYTES (4 * STAGE_HALFS * 2 * 2)

__global__ void __launch_bounds__(128, 2)
gemm_f16(const __half* __restrict__ A, const __half* __restrict__ W,
         const float* __restrict__ bias, const float* __restrict__ res,
         float* __restrict__ C, __half* __restrict__ Ch,
         int M, int Nn, int K, int relu) {
    extern __shared__ __half smemh[];
    __half* SA = smemh;
    __half* SB = smemh + 4 * STAGE_HALFS;
    uint32_t sa_u = (uint32_t)__cvta_generic_to_shared(SA);
    uint32_t sb_u = (uint32_t)__cvta_generic_to_shared(SB);

    int tid = threadIdx.x;
    int wid = tid >> 5, lane = tid & 31;
    int g = lane >> 2, t = lane & 3;
    int wm = wid >> 1, wn = wid & 1;
    int bm = blockIdx.y * 128, bn = blockIdx.x * 128;

    int lrow = tid >> 2, lc = tid & 3;
    const __half* Ag = A + (size_t)(bm + lrow) * K + lc * 8;
    const __half* Wg = W + (size_t)(bn + lrow) * K + lc * 8;
    uint32_t soff = (uint32_t)(lrow * SSTH * 2 + lc * 16);

    int arow = (lane & 7) + ((lane >> 3) & 1) * 8;
    int acol = (lane >> 4) * 8;
    int brow = (lane & 7) + (lane >> 4) * 8;
    int bcol = ((lane >> 3) & 1) * 8;

    float acc[4][8][4];
    #pragma unroll
    for (int i = 0; i < 4; i++)
        #pragma unroll
        for (int j = 0; j < 8; j++)
            #pragma unroll
            for (int v = 0; v < 4; v++) acc[i][j][v] = 0.f;

    int S = K / BK;

    auto issue = [&](int s) {
        int st = s & 3;
        int koff = s * BK;
        uint32_t sbase = (uint32_t)(st * STAGE_HALFS * 2) + soff;
        #pragma unroll
        for (int i = 0; i < 4; i++) {
            cp16(sa_u + sbase + i * 32 * SSTH * 2, Ag + (size_t)i * 32 * K + koff);
            cp16(sb_u + sbase + i * 32 * SSTH * 2, Wg + (size_t)i * 32 * K + koff);
        }
        CP_COMMIT();
    };

    issue(0); issue(1); issue(2);

    for (int s = 0; s < S; s++) {
        CP_WAIT2();
        __syncthreads();
        if (s + 3 < S) issue(s + 3);
        else CP_COMMIT();

        int st = s & 3;
        uint32_t sa_st = sa_u + (uint32_t)(st * STAGE_HALFS * 2);
        uint32_t sb_st = sb_u + (uint32_t)(st * STAGE_HALFS * 2);
        #pragma unroll
        for (int ks = 0; ks < 2; ks++) {
            int k0 = ks * 16;
            uint32_t af[4][4];
            #pragma unroll
            for (int mi = 0; mi < 4; mi++) {
                int r0 = wm * 64 + mi * 16;
                ldm_x4(af[mi], sa_st + (uint32_t)(((r0 + arow) * SSTH + k0 + acol) * 2));
            }
            uint32_t bf[8][2];
            #pragma unroll
            for (int np = 0; np < 4; np++) {
                int n0 = wn * 64 + np * 16;
                uint32_t br[4];
                ldm_x4(br, sb_st + (uint32_t)(((n0 + brow) * SSTH + k0 + bcol) * 2));
                bf[np * 2 + 0][0] = br[0]; bf[np * 2 + 0][1] = br[1];
                bf[np * 2 + 1][0] = br[2]; bf[np * 2 + 1][1] = br[3];
            }
            #pragma unroll
            for (int mi = 0; mi < 4; mi++)
                #pragma unroll
                for (int ni = 0; ni < 8; ni++)
                    mma_f16(acc[mi][ni], af[mi], bf[ni]);
        }
    }

    #pragma unroll
    for (int mi = 0; mi < 4; mi++) {
        int r0 = bm + wm * 64 + mi * 16 + g;
        #pragma unroll
        for (int half_ = 0; half_ < 2; half_++) {
            int row = r0 + half_ * 8;
            const float* rrow = res ? res + (size_t)row * Nn + bn + wn * 64 : nullptr;
            const float* brow_ = bias + bn + wn * 64;
            #pragma unroll
            for (int ni = 0; ni < 8; ni++) {
                int col = ni * 8 + 2 * t;
                float v0 = acc[mi][ni][half_ * 2 + 0] + brow_[col];
                float v1 = acc[mi][ni][half_ * 2 + 1] + brow_[col + 1];
                if (relu) { v0 = fmaxf(v0, 0.f); v1 = fmaxf(v1, 0.f); }
                if (rrow) { v0 += rrow[col]; v1 += rrow[col + 1]; }
                if (Ch) {
                    __half2 hh = __floats2half2_rn(v0, v1);
                    *(uint32_t*)(Ch + (size_t)row * Nn + bn + wn * 64 + col) =
                        *(uint32_t*)&hh;
                } else {
                    *(float2*)(C + (size_t)row * Nn + bn + wn * 64 + col) =
                        make_float2(v0, v1);
                }
            }
        }
    }
}

// ---------------- fp16 tensor-core windowed attention, 64-key tiles ----------
// smem (halfs): Kh[2][64][72] | Vh[2][64][72] | Ps[128][72] | rp_s[512 floats]
#define AKST 72
#define ATILE 64
#define AK_ELTS (ATILE * AKST)
#define ASMEM_BYTES ((4 * AK_ELTS + 128 * AKST) * 2 + MAXLEN * 4)

__global__ void __launch_bounds__(256)
attn_kernel(const __half* __restrict__ qkv, const float* __restrict__ rel_pos,
            __half* __restrict__ o) {
    extern __shared__ __half ash[];
    __half* Kh = ash;
    __half* Vh = ash + 2 * AK_ELTS;
    __half* Ps = ash + 4 * AK_ELTS;
    float* rp_s = (float*)(ash + 4 * AK_ELTS + 128 * AKST);
    uint32_t kh_u = (uint32_t)__cvta_generic_to_shared(Kh);
    uint32_t vh_u = (uint32_t)__cvta_generic_to_shared(Vh);
    uint32_t ps_u = (uint32_t)__cvta_generic_to_shared(Ps);

    int tid = threadIdx.x;
    int wid = tid >> 5, lane = tid & 31;
    int g = lane >> 2, t = lane & 3;
    int b = blockIdx.z, h = blockIdx.y;
    int qs = blockIdx.x * 128;
    const __half* base = qkv + (size_t)b * N_ * 3 * E_;
    const float* rp = rel_pos + h * MAXLEN;

    // bias row into smem (512 floats)
    rp_s[tid] = rp[tid];
    rp_s[tid + 256] = rp[tid + 256];

    int row0 = qs + wid * 16 + g;
    int row_lo = qs + wid * 16;
    uint32_t qf[4][4];
    {
        const __half* q0 = base + (size_t)row0 * 3 * E_ + h * DH;
        const __half* q1 = q0 + (size_t)8 * 3 * E_;
        #pragma unroll
        for (int kk = 0; kk < 4; kk++) {
            qf[kk][0] = *(const uint32_t*)(q0 + kk * 16 + 2 * t);
            qf[kk][1] = *(const uint32_t*)(q1 + kk * 16 + 2 * t);
            qf[kk][2] = *(const uint32_t*)(q0 + kk * 16 + 8 + 2 * t);
            qf[kk][3] = *(const uint32_t*)(q1 + kk * 16 + 8 + 2 * t);
        }
    }

    float oacc[8][4];
    #pragma unroll
    for (int i = 0; i < 8; i++)
        #pragma unroll
        for (int v = 0; v < 4; v++) oacc[i][v] = 0.f;
    float m_o[2] = {-INFINITY, -INFINITY};
    float lac[2] = {0.f, 0.f};

    int kt_lo = max(0, qs - (MAXLEN - 1)) >> 6;
    int kt_hi = (qs + 127) >> 6;

    int jrow = tid >> 2;
    int jc = (tid & 3) * 16;
    const __half* kgbase = base + E_ + h * DH + jc;
    const __half* vgbase = base + 2 * E_ + h * DH + jc;

    auto issueKV = [&](int kt, int buf) {
        int ks0 = kt * ATILE;
        const __half* kp = kgbase + (size_t)(ks0 + jrow) * 3 * E_;
        const __half* vp = vgbase + (size_t)(ks0 + jrow) * 3 * E_;
        uint32_t kd = kh_u + (uint32_t)((buf * AK_ELTS + jrow * AKST + jc) * 2);
        uint32_t vd = vh_u + (uint32_t)((buf * AK_ELTS + jrow * AKST + jc) * 2);
        cp16(kd, kp); cp16(kd + 16, kp + 8);
        cp16(vd, vp); cp16(vd + 16, vp + 8);
        CP_COMMIT();
    };

    issueKV(kt_lo, 0);

    int brow = (lane & 7) + (lane >> 4) * 8;
    int bcol = ((lane >> 3) & 1) * 8;
    int arow = (lane & 7) + ((lane >> 3) & 1) * 8;
    int acol = (lane >> 4) * 8;
    int vdg = (lane >> 4) & 1;
    int vkg = (lane >> 3) & 1;
    int vrr = lane & 7;
    int lrow0 = wid * 16 + g;

    for (int kt = kt_lo; kt <= kt_hi; kt++) {
        int buf = (kt - kt_lo) & 1;
        __syncthreads();
        if (kt + 1 <= kt_hi) issueKV(kt + 1, buf ^ 1);
        else CP_COMMIT();
        CP_WAIT1();
        __syncthreads();

        int ks0 = kt * ATILE;
        if (ks0 > row_lo + 15 || ks0 + (ATILE - 1) < row_lo - (MAXLEN - 1))
            continue;

        uint32_t kb = kh_u + (uint32_t)(buf * AK_ELTS * 2);
        uint32_t vb = vh_u + (uint32_t)(buf * AK_ELTS * 2);

        // ---- S = Q K^T (16 x 64 per warp) ----
        float sacc[8][4];
        #pragma unroll
        for (int ni = 0; ni < 8; ni++)
            #pragma unroll
            for (int v = 0; v < 4; v++) sacc[ni][v] = 0.f;
        #pragma unroll
        for (int kk = 0; kk < 4; kk++) {
            int k0 = kk * 16;
            uint32_t bf[8][2];
            #pragma unroll
            for (int np = 0; np < 4; np++) {
                uint32_t br[4];
                ldm_x4(br, kb + (uint32_t)(((np * 16 + brow) * AKST + k0 + bcol) * 2));
                bf[np * 2 + 0][0] = br[0]; bf[np * 2 + 0][1] = br[1];
                bf[np * 2 + 1][0] = br[2]; bf[np * 2 + 1][1] = br[3];
            }
            #pragma unroll
            for (int ni = 0; ni < 8; ni++)
                mma_f16(sacc[ni], qf[kk], bf[ni]);
        }

        // ---- scale + bias (+mask on boundary) + online softmax ----
        int drel = row0 - ks0 - 2 * t;   // rel = drel + r*8 - ni*8 - (v&1)
        float m_t[2] = {-INFINITY, -INFINITY};
        bool interior = (ks0 <= row_lo - 63) && (ks0 >= row_lo - (MAXLEN - 16));
        if (interior) {
            #pragma unroll
            for (int ni = 0; ni < 8; ni++) {
                #pragma unroll
                for (int v = 0; v < 4; v++) {
                    int r = v >> 1;
                    float val = sacc[ni][v] * 0.125f
                              + rp_s[drel + r * 8 - ni * 8 - (v & 1)];
                    sacc[ni][v] = val;
                    m_t[r] = fmaxf(m_t[r], val);
                }
            }
        } else {
            #pragma unroll
            for (int ni = 0; ni < 8; ni++) {
                #pragma unroll
                for (int v = 0; v < 4; v++) {
                    int r = v >> 1;
                    int rel = drel + r * 8 - ni * 8 - (v & 1);
                    float val;
                    if (rel >= 0 && rel < MAXLEN)
                        val = sacc[ni][v] * 0.125f + rp_s[rel];
                    else
                        val = -INFINITY;
                    sacc[ni][v] = val;
                    m_t[r] = fmaxf(m_t[r], val);
                }
            }
        }
        #pragma unroll
        for (int r = 0; r < 2; r++) {
            m_t[r] = fmaxf(m_t[r], __shfl_xor_sync(0xffffffffu, m_t[r], 1));
            m_t[r] = fmaxf(m_t[r], __shfl_xor_sync(0xffffffffu, m_t[r], 2));
        }
        float fac[2], m_n[2];
        #pragma unroll
        for (int r = 0; r < 2; r++) {
            m_n[r] = fmaxf(m_o[r], m_t[r]);
            fac[r] = (m_n[r] == -INFINITY) ? 1.f : __expf(m_o[r] - m_n[r]);
            if (m_o[r] == -INFINITY) fac[r] = 0.f;
            if (m_n[r] == -INFINITY) fac[r] = 1.f;
        }
        float psum[2] = {0.f, 0.f};
        #pragma unroll
        for (int ni = 0; ni < 8; ni++) {
            #pragma unroll
            for (int r = 0; r < 2; r++) {
                float p0 = (m_n[r] == -INFINITY) ? 0.f
                           : __expf(sacc[ni][r * 2 + 0] - m_n[r]);
                float p1 = (m_n[r] == -INFINITY) ? 0.f
                           : __expf(sacc[ni][r * 2 + 1] - m_n[r]);
                psum[r] += p0 + p1;
                __half2 ph = __floats2half2_rn(p0, p1);
                *(uint32_t*)&Ps[(lrow0 + r * 8) * AKST + ni * 8 + 2 * t] =
                    *(uint32_t*)&ph;
            }
        }
        #pragma unroll
        for (int r = 0; r < 2; r++) {
            psum[r] += __shfl_xor_sync(0xffffffffu, psum[r], 1);
            psum[r] += __shfl_xor_sync(0xffffffffu, psum[r], 2);
            lac[r] = lac[r] * fac[r] + psum[r];
            m_o[r] = m_n[r];
        }
        #pragma unroll
        for (int i = 0; i < 8; i++) {
            oacc[i][0] *= fac[0]; oacc[i][1] *= fac[0];
            oacc[i][2] *= fac[1]; oacc[i][3] *= fac[1];
        }
        __syncwarp();

        // ---- O += P V (k = 64) ----
        #pragma unroll
        for (int kk = 0; kk < 4; kk++) {
            int k0 = kk * 16;
            uint32_t af[4];
            ldm_x4(af, ps_u + (uint32_t)(((wid * 16 + arow) * AKST + k0 + acol) * 2));
            #pragma unroll
            for (int np = 0; np < 4; np++) {
                uint32_t br[4];
                ldm_x4t(br, vb + (uint32_t)(((k0 + vkg * 8 + vrr) * AKST
                                             + np * 16 + vdg * 8) * 2));
                uint32_t b0[2] = {br[0], br[1]};
                uint32_t b1[2] = {br[2], br[3]};
                mma_f16(oacc[np * 2 + 0], af, b0);
                mma_f16(oacc[np * 2 + 1], af, b1);
            }
        }
        __syncwarp();
    }

    float inv0 = 1.f / lac[0];
    float inv1 = 1.f / lac[1];
    __half* op0 = o + ((size_t)(b * N_) + row0) * E_ + h * DH;
    __half* op1 = op0 + (size_t)8 * E_;
    #pragma unroll
    for (int ni = 0; ni < 8; ni++) {
        int col = ni * 8 + 2 * t;
        __half2 h0 = __floats2half2_rn(oacc[ni][0] * inv0, oacc[ni][1] * inv0);
        __half2 h1 = __floats2half2_rn(oacc[ni][2] * inv1, oacc[ni][3] * inv1);
        *(uint32_t*)(op0 + col) = *(uint32_t*)&h0;
        *(uint32_t*)(op1 + col) = *(uint32_t*)&h1;
    }
}

// ---------------- driver ----------------
extern "C" void kernel_launch(void* const* d_in, const int* in_sizes, int n_in,
                              void* d_out, int out_size) {
    const float* x         = (const float*)d_in[0];
    const float* rel_pos   = (const float*)d_in[1];
    const float* in_proj_w = (const float*)d_in[2];
    const float* in_proj_b = (const float*)d_in[3];
    const float* out_w     = (const float*)d_in[4];
    const float* out_b     = (const float*)d_in[5];
    const float* w1        = (const float*)d_in[6];
    const float* b1        = (const float*)d_in[7];
    const float* w2        = (const float*)d_in[8];
    const float* b2        = (const float*)d_in[9];
    const float* ln1_g     = (const float*)d_in[10];
    const float* ln1_b     = (const float*)d_in[11];
    const float* ln2_g     = (const float*)d_in[12];
    const float* ln2_b     = (const float*)d_in[13];
    float* out = (float*)d_out;

    __half *xn, *qkv, *o, *xm, *hbuf, *wqkv, *wout, *w1h, *w2h;
    cudaGetSymbolAddress((void**)&xn,   g_xn);
    cudaGetSymbolAddress((void**)&qkv,  g_qkv);
    cudaGetSymbolAddress((void**)&o,    g_o);
    cudaGetSymbolAddress((void**)&xm,   g_xm);
    cudaGetSymbolAddress((void**)&hbuf, g_hbuf);
    cudaGetSymbolAddress((void**)&wqkv, g_wqkv);
    cudaGetSymbolAddress((void**)&wout, g_wout);
    cudaGetSymbolAddress((void**)&w1h,  g_w1);
    cudaGetSymbolAddress((void**)&w2h,  g_w2);

    cudaFuncSetAttribute(gemm_f16, cudaFuncAttributeMaxDynamicSharedMemorySize,
                         GSMEM_BYTES);
    cudaFuncSetAttribute(attn_kernel, cudaFuncAttributeMaxDynamicSharedMemorySize,
                         ASMEM_BYTES);

    cvt_all_kernel<<<12 * E_ * E_ / 1024, 256>>>(in_proj_w, out_w, w1, w2,
                                                 wqkv, wout, w1h, w2h);

    ln_kernel<<<ROWS, 256>>>(x, ln1_g, ln1_b, xn);
    gemm_f16<<<dim3(3 * E_ / 128, ROWS / 128), 128, GSMEM_BYTES>>>(
        xn, wqkv, in_proj_b, nullptr, nullptr, qkv, ROWS, 3 * E_, E_, 0);
    attn_kernel<<<dim3(N_ / 128, H_, B_), 256, ASMEM_BYTES>>>(qkv, rel_pos, o);
    gemm_f16<<<dim3(E_ / 128, ROWS / 128), 128, GSMEM_BYTES>>>(
        o, wout, out_b, x, out, nullptr, ROWS, E_, E_, 0);
    ln_kernel<<<ROWS, 256>>>(out, ln2_g, ln2_b, xm);
    gemm_f16<<<dim3(FF / 128, ROWS / 128), 128, GSMEM_BYTES>>>(
        xm, w1h, b1, nullptr, nullptr, hbuf, ROWS, FF, E_, 1);
    gemm_f16<<<dim3(E_ / 128, ROWS / 128), 128, GSMEM_BYTES>>>(
        hbuf, w2h, b2, out, out, nullptr, ROWS, E_, FF, 0);
}